// round 10
// baseline (speedup 1.0000x reference)
#include <cuda_runtime.h>
#include <cuda_bf16.h>
#include <cuda_fp16.h>
#include <math.h>
#include <cstdint>

// Problem constants
#define BB 2
#define TT 2048
#define DM 1024
#define HH 16
#define DD 64
#define NQKV 5120     // H * 5 * D
#define BT  4096      // B * T
#define KW  2048      // A operand: [hi(1024) | lo(1024)] fp16
#define KB  1024      // B operand: single fp16 plane

// ---------------- scratch (no cudaMalloc allowed) ----------------
__device__ __align__(16) float g_qkv[(size_t)BT * NQKV];               // 83.9 MB
__device__ __align__(16) __half g_Af [(size_t)BT * KW];                // 16.8 MB (x-split, then attn-split)
__device__ __align__(16) __half g_Bqf[(size_t)NQKV * KB];              // 10.5 MB
__device__ __align__(16) __half g_Bof[(size_t)DM * KB];                // 2.1 MB
// flash operands (fp16 single-plane): [bh][t][64], V^T [bh][d][t]
__device__ __align__(16) __half g_Q1f[(size_t)BB * HH * TT * DD];
__device__ __align__(16) __half g_Q2f[(size_t)BB * HH * TT * DD];
__device__ __align__(16) __half g_K1f[(size_t)BB * HH * TT * DD];
__device__ __align__(16) __half g_K2f[(size_t)BB * HH * TT * DD];
__device__ __align__(16) __half g_Vt [(size_t)BB * HH * DD * TT];

// ================= helpers (plain sm_103-safe PTX only) =================
__device__ __forceinline__ uint32_t smem_u32(const void* p) {
    uint32_t a;
    asm("{ .reg .u64 t; cvta.to.shared.u64 t, %1; cvt.u32.u64 %0, t; }" : "=r"(a) : "l"(p));
    return a;
}
#define CP16(smem, gptr) \
    asm volatile("cp.async.cg.shared.global [%0], [%1], 16;" :: "r"(smem), "l"(gptr) : "memory")
#define CP_COMMIT() asm volatile("cp.async.commit_group;" ::: "memory")
#define CP_WAIT(n)  asm volatile("cp.async.wait_group %0;" :: "n"(n) : "memory")
#define LDSM_X4(r0, r1, r2, r3, addr) \
    asm volatile("ldmatrix.sync.aligned.m8n8.x4.shared.b16 {%0,%1,%2,%3}, [%4];" \
                 : "=r"(r0), "=r"(r1), "=r"(r2), "=r"(r3) : "r"(addr))
#define MMAH16816(c, a, b) \
    asm volatile("mma.sync.aligned.m16n8k16.row.col.f32.f16.f16.f32 " \
                 "{%0,%1,%2,%3}, {%4,%5,%6,%7}, {%8,%9}, {%0,%1,%2,%3};" \
                 : "+f"((c)[0]), "+f"((c)[1]), "+f"((c)[2]), "+f"((c)[3]) \
                 : "r"((a)[0]), "r"((a)[1]), "r"((a)[2]), "r"((a)[3]), \
                   "r"((b)[0]), "r"((b)[1]))

__device__ __forceinline__ uint32_t packh(float lo, float hi) {
    __half2 t = __floats2half2_rn(lo, hi);
    return *(uint32_t*)&t;
}

// ================= conversion kernels =================
// fp32 [M,1024] row-major -> fp16 [M,2048]: cols [0,1024)=hi [1024,2048)=lo (exact residual)
__global__ void __launch_bounds__(256) split_rows(const float* __restrict__ in,
                                                  __half* __restrict__ out, int total) {
    int idx = blockIdx.x * 256 + threadIdx.x;
    if (idx >= total) return;
    int m = idx >> 10, k = idx & 1023;
    float v = in[idx];
    __half h = __float2half(v);
    __half l = __float2half(v - __half2float(h));
    size_t rb = (size_t)m * KW;
    out[rb + k] = h;
    out[rb + 1024 + k] = l;
}

// W fp32 [1024, N] -> fp16 [N, 1024] transposed (single plane)
__global__ void __launch_bounds__(256) splitT(const float* __restrict__ W,
                                              __half* __restrict__ out, int N) {
    __shared__ float smt[32][33];
    int n0 = blockIdx.x * 32, k0 = blockIdx.y * 32;
    int tx = threadIdx.x, ty = threadIdx.y;  // 32 x 8
#pragma unroll
    for (int i = 0; i < 4; i++)
        smt[ty * 4 + i][tx] = W[(size_t)(k0 + ty * 4 + i) * N + n0 + tx];
    __syncthreads();
#pragma unroll
    for (int i = 0; i < 4; i++) {
        int nn = ty * 4 + i;
        out[(size_t)(n0 + nn) * KB + k0 + tx] = __float2half(smt[tx][nn]);
    }
}

// g_qkv fp32 -> Q1/Q2/K1/K2 fp16 [bh][t][64]
__global__ void __launch_bounds__(256) qkv_split(const float* __restrict__ qkv,
                                                 __half* __restrict__ Q1,
                                                 __half* __restrict__ Q2,
                                                 __half* __restrict__ K1,
                                                 __half* __restrict__ K2) {
    int idx = blockIdx.x * 256 + threadIdx.x;           // over bh*T*64
    if (idx >= BB * HH * TT * DD) return;
    int d = idx & 63;
    int t = (idx >> 6) & (TT - 1);
    int bh = idx >> 17;
    int b = bh >> 4, h = bh & 15;
    const float* src = qkv + (size_t)(b * TT + t) * NQKV + h * 320 + d;
    size_t dst = ((size_t)bh * TT + t) * DD + d;
    Q1[dst] = __float2half(src[0]);
    Q2[dst] = __float2half(src[64]);
    K1[dst] = __float2half(src[128]);
    K2[dst] = __float2half(src[192]);
}

// V fp32 [t, d] -> V^T fp16 [bh][d][t]
__global__ void __launch_bounds__(256) v_transpose(const float* __restrict__ qkv,
                                                   __half* __restrict__ Vt) {
    __shared__ float tile[64][65];
    int t0 = blockIdx.x * 64;
    int bh = blockIdx.y;
    int b = bh >> 4, h = bh & 15;
    int c = threadIdx.x & 63, r4 = threadIdx.x >> 6;
#pragma unroll
    for (int rr = r4; rr < 64; rr += 4)
        tile[rr][c] = qkv[(size_t)(b * TT + t0 + rr) * NQKV + h * 320 + 256 + c];
    __syncthreads();
#pragma unroll
    for (int dd = r4; dd < 64; dd += 4)
        Vt[((size_t)bh * DD + dd) * TT + t0 + c] = __float2half(tile[c][dd]);
}

// ========== 2-combo fp16 HMMA GEMM: C[M,N] = (Ah+Al)[M,1024] @ B[N,1024]^T ==========
// A stored [rows][hi(1024)|lo(1024)] fp16; B [rows][1024] fp16.
// 128x128 CTA tile, 8 warps (4m x 2n), warp tile 32x64. 3-stage cp.async pipeline.
#define BKC 64
#define NKI (1024 / BKC)      // 16
#define ASTR 72               // smem row stride in fp16
#define TILE_E (128 * ASTR)   // one 128x64 tile (padded)
#define STAGE_E (3 * TILE_E)  // Ah | Al | B
#define NSTAGE 3
#define GEMM_SMEM (NSTAGE * STAGE_E * 2)   // 165888 bytes

__global__ void __launch_bounds__(256) gemm_mma(const __half* __restrict__ A,
                                                const __half* __restrict__ B,
                                                float* __restrict__ C, int Ntot) {
    extern __shared__ __half smb[];
    const int tid = threadIdx.x;
    const int wid = tid >> 5;
    const int lane = tid & 31;
    const int m0 = blockIdx.y * 128;
    const int n0 = blockIdx.x * 128;
    const int wm = (wid >> 1) * 32;
    const int wn = (wid & 1) * 64;
    const uint32_t sbase = smem_u32(smb);

    const int ldrow = tid >> 1;
    const int ldcol = (tid & 1) * 32;
    const __half* Agp = A + (size_t)(m0 + ldrow) * KW + ldcol;
    const __half* Bgp = B + (size_t)(n0 + ldrow) * KB + ldcol;
    const uint32_t st_off = (uint32_t)(ldrow * ASTR + ldcol) * 2;

    uint32_t aoff[2], boff[4];
#pragma unroll
    for (int mt = 0; mt < 2; mt++) {
        int row = wm + mt * 16 + (lane & 15);
        int col = (lane >> 4) * 8;
        aoff[mt] = (uint32_t)(row * ASTR + col) * 2;
    }
#pragma unroll
    for (int nt2 = 0; nt2 < 4; nt2++) {
        int n = wn + nt2 * 16 + ((lane >> 4) & 1) * 8 + (lane & 7);
        int k = ((lane >> 3) & 1) * 8;
        boff[nt2] = (uint32_t)(n * ASTR + k) * 2;
    }

    float acc[2][8][4];
#pragma unroll
    for (int mt = 0; mt < 2; mt++)
#pragma unroll
        for (int nt = 0; nt < 8; nt++)
#pragma unroll
            for (int j = 0; j < 4; j++) acc[mt][nt][j] = 0.f;

#define LOAD_STAGE(s, k0)                                                          \
    do {                                                                           \
        uint32_t _b = sbase + (uint32_t)(s) * STAGE_E * 2 + st_off;                \
        const __half* _a = Agp + (k0);                                             \
        const __half* _bb = Bgp + (k0);                                            \
        _Pragma("unroll")                                                          \
        for (int j = 0; j < 4; j++) {                                              \
            CP16(_b + j * 16, _a + j * 8);                                         \
            CP16(_b + TILE_E * 2 + j * 16, _a + 1024 + j * 8);                     \
            CP16(_b + 2 * TILE_E * 2 + j * 16, _bb + j * 8);                       \
        }                                                                          \
    } while (0)

    LOAD_STAGE(0, 0);
    CP_COMMIT();
    LOAD_STAGE(1, BKC);
    CP_COMMIT();

    for (int i = 0; i < NKI; i++) {
        if (i + 1 < NKI) { CP_WAIT(1); } else { CP_WAIT(0); }
        __syncthreads();
        if (i + 2 < NKI) {
            LOAD_STAGE((i + 2) % NSTAGE, (i + 2) * BKC);
            CP_COMMIT();
        }
        const uint32_t stAh = sbase + (uint32_t)(i % NSTAGE) * STAGE_E * 2;
        const uint32_t stAl = stAh + TILE_E * 2;
        const uint32_t stB  = stAh + 2 * TILE_E * 2;
#pragma unroll
        for (int ks = 0; ks < 4; ks++) {
            uint32_t ah[2][4], al[2][4], bf[4][4];
#pragma unroll
            for (int mt = 0; mt < 2; mt++) {
                LDSM_X4(ah[mt][0], ah[mt][1], ah[mt][2], ah[mt][3], stAh + aoff[mt] + ks * 32);
                LDSM_X4(al[mt][0], al[mt][1], al[mt][2], al[mt][3], stAl + aoff[mt] + ks * 32);
            }
#pragma unroll
            for (int nt2 = 0; nt2 < 4; nt2++)
                LDSM_X4(bf[nt2][0], bf[nt2][1], bf[nt2][2], bf[nt2][3], stB + boff[nt2] + ks * 32);
#pragma unroll
            for (int mt = 0; mt < 2; mt++)
#pragma unroll
                for (int nt2 = 0; nt2 < 4; nt2++) {
                    MMAH16816(acc[mt][2 * nt2],     ah[mt], (&bf[nt2][0]));
                    MMAH16816(acc[mt][2 * nt2 + 1], ah[mt], (&bf[nt2][2]));
                    MMAH16816(acc[mt][2 * nt2],     al[mt], (&bf[nt2][0]));
                    MMAH16816(acc[mt][2 * nt2 + 1], al[mt], (&bf[nt2][2]));
                }
        }
    }
#undef LOAD_STAGE

#pragma unroll
    for (int mt = 0; mt < 2; mt++) {
        int r0 = m0 + wm + mt * 16 + (lane >> 2);
        int c0 = n0 + wn + (lane & 3) * 2;
        float* p0 = C + (size_t)r0 * Ntot + c0;
        float* p1 = C + (size_t)(r0 + 8) * Ntot + c0;
#pragma unroll
        for (int nt = 0; nt < 8; nt++) {
            *(float2*)(p0 + nt * 8) = make_float2(acc[mt][nt][0], acc[mt][nt][1]);
            *(float2*)(p1 + nt * 8) = make_float2(acc[mt][nt][2], acc[mt][nt][3]);
        }
    }
}

// ================= fp16 HMMA dual flash attention =================
// CTA: 128 q-rows of one (b,h); 8 warps, warp = m16. kv tiles of 64, double-buffered.
#define QS2 72                        // fp16 row stride (144B)
#define FL_Q1 0
#define FL_Q2 (128 * QS2)
#define FL_ST0 (2 * 128 * QS2)
#define FL_KV (64 * QS2)              // one tensor in a stage
#define FL_STAGE (3 * FL_KV)          // K1 | K2 | Vt
#define FL_SMEM_BYTES ((2 * 128 * QS2 + 2 * FL_STAGE) * 2)   // 92160

__device__ __forceinline__ void fl_load_kv(uint32_t sb, int st, int kt, int tid,
                                           const __half* K1g,
                                           const __half* K2g,
                                           const __half* Vg) {
    int r = tid >> 2, qd = tid & 3;   // row 0..63, 16-elem quarter
    uint32_t base = sb + (uint32_t)(FL_ST0 + st * FL_STAGE) * 2;
    uint32_t o = (uint32_t)(r * QS2 + qd * 16) * 2;
    const __half* k1 = K1g + (size_t)(kt * 64 + r) * DD + qd * 16;
    const __half* k2 = K2g + (size_t)(kt * 64 + r) * DD + qd * 16;
    const __half* vv = Vg + (size_t)r * TT + kt * 64 + qd * 16;
#pragma unroll
    for (int j = 0; j < 2; j++) {
        CP16(base + o + j * 16, k1 + j * 8);
        CP16(base + FL_KV * 2 + o + j * 16, k2 + j * 8);
        CP16(base + 2 * FL_KV * 2 + o + j * 16, vv + j * 8);
    }
}

// one stream: S = Q K^T (fp16), online softmax, O += P V (fp16)
__device__ __forceinline__ void fl_stream(uint32_t a_addr, uint32_t kstage, uint32_t vstage,
                                          uint32_t b_lane_b, int kt, bool need_mask,
                                          int row_g0, int lane,
                                          float O[8][4], float* mst, float* lst) {
    float acc[8][4];
#pragma unroll
    for (int nb = 0; nb < 8; nb++)
#pragma unroll
        for (int j = 0; j < 4; j++) acc[nb][j] = 0.f;

    // S = Q K^T, 4 k16 steps over D=64
#pragma unroll
    for (int s = 0; s < 4; s++) {
        uint32_t af[4];
        LDSM_X4(af[0], af[1], af[2], af[3], a_addr + s * 32);
#pragma unroll
        for (int nt2 = 0; nt2 < 4; nt2++) {
            uint32_t bf[4];
            LDSM_X4(bf[0], bf[1], bf[2], bf[3],
                    kstage + b_lane_b + (uint32_t)(nt2 * 16 * QS2 + s * 16) * 2);
            MMAH16816(acc[2 * nt2],     af, (&bf[0]));
            MMAH16816(acc[2 * nt2 + 1], af, (&bf[2]));
        }
    }

    // scale + causal mask
#pragma unroll
    for (int nb = 0; nb < 8; nb++)
#pragma unroll
        for (int j = 0; j < 4; j++) {
            float v = acc[nb][j] * 0.125f;
            if (need_mask) {
                int col = kt * 64 + nb * 8 + 2 * (lane & 3) + (j & 1);
                int row = row_g0 + ((j >> 1) << 3);
                if (col > row) v = -1e30f;
            }
            acc[nb][j] = v;
        }

    // online softmax (rows r and r+8)
    float mx0 = -1e30f, mx1 = -1e30f;
#pragma unroll
    for (int nb = 0; nb < 8; nb++) {
        mx0 = fmaxf(mx0, fmaxf(acc[nb][0], acc[nb][1]));
        mx1 = fmaxf(mx1, fmaxf(acc[nb][2], acc[nb][3]));
    }
    mx0 = fmaxf(mx0, __shfl_xor_sync(0xffffffffu, mx0, 1));
    mx0 = fmaxf(mx0, __shfl_xor_sync(0xffffffffu, mx0, 2));
    mx1 = fmaxf(mx1, __shfl_xor_sync(0xffffffffu, mx1, 1));
    mx1 = fmaxf(mx1, __shfl_xor_sync(0xffffffffu, mx1, 2));
    float mn0 = fmaxf(mst[0], mx0), mn1 = fmaxf(mst[1], mx1);
    float al0 = __expf(mst[0] - mn0), al1 = __expf(mst[1] - mn1);
    float s0 = 0.f, s1 = 0.f;
#pragma unroll
    for (int nb = 0; nb < 8; nb++) {
        acc[nb][0] = __expf(acc[nb][0] - mn0);
        acc[nb][1] = __expf(acc[nb][1] - mn0);
        acc[nb][2] = __expf(acc[nb][2] - mn1);
        acc[nb][3] = __expf(acc[nb][3] - mn1);
        s0 += acc[nb][0] + acc[nb][1];
        s1 += acc[nb][2] + acc[nb][3];
    }
    s0 += __shfl_xor_sync(0xffffffffu, s0, 1);
    s0 += __shfl_xor_sync(0xffffffffu, s0, 2);
    s1 += __shfl_xor_sync(0xffffffffu, s1, 1);
    s1 += __shfl_xor_sync(0xffffffffu, s1, 2);
    lst[0] = lst[0] * al0 + s0;
    lst[1] = lst[1] * al1 + s1;
    mst[0] = mn0;
    mst[1] = mn1;
#pragma unroll
    for (int nb = 0; nb < 8; nb++) {
        O[nb][0] *= al0; O[nb][1] *= al0;
        O[nb][2] *= al1; O[nb][3] *= al1;
    }

    // O += P V (register-direct fp16 P fragments)
#pragma unroll
    for (int s = 0; s < 4; s++) {
        uint32_t ah[4];
        ah[0] = packh(acc[2 * s][0],     acc[2 * s][1]);
        ah[1] = packh(acc[2 * s][2],     acc[2 * s][3]);
        ah[2] = packh(acc[2 * s + 1][0], acc[2 * s + 1][1]);
        ah[3] = packh(acc[2 * s + 1][2], acc[2 * s + 1][3]);
#pragma unroll
        for (int nt2 = 0; nt2 < 4; nt2++) {
            uint32_t bv[4];
            LDSM_X4(bv[0], bv[1], bv[2], bv[3],
                    vstage + b_lane_b + (uint32_t)(nt2 * 16 * QS2 + s * 16) * 2);
            MMAH16816(O[2 * nt2],     ah, (&bv[0]));
            MMAH16816(O[2 * nt2 + 1], ah, (&bv[2]));
        }
    }
}

__global__ void __launch_bounds__(256) flash_mma(
    const __half* __restrict__ Q1f, const __half* __restrict__ Q2f,
    const __half* __restrict__ K1f, const __half* __restrict__ K2f,
    const __half* __restrict__ Vtg, const float* __restrict__ lam_p,
    __half* __restrict__ Af) {
    extern __shared__ __half sfb[];
    const uint32_t sb = smem_u32(sfb);
    const int tid = threadIdx.x, wid = tid >> 5, lane = tid & 31;
    const int qrev = gridDim.x - 1 - blockIdx.x;    // heavy CTAs first
    const int q0 = qrev * 128;
    const int h = blockIdx.y, b = blockIdx.z;
    const int bh = b * HH + h;
    const int nkv = 2 * qrev + 2;

    const __half* Q1g = Q1f + ((size_t)bh * TT + q0) * DD;
    const __half* Q2g = Q2f + ((size_t)bh * TT + q0) * DD;
    const __half* K1g = K1f + (size_t)bh * TT * DD;
    const __half* K2g = K2f + (size_t)bh * TT * DD;
    const __half* Vg  = Vtg + (size_t)bh * DD * TT;

    // Q tiles via cp.async: 128 rows x 64 fp16
    {
        int row = tid >> 1, seg = (tid & 1) * 32;
        uint32_t d1 = sb + (uint32_t)(FL_Q1 + row * QS2 + seg) * 2;
        uint32_t d2 = sb + (uint32_t)(FL_Q2 + row * QS2 + seg) * 2;
        const __half* s1 = Q1g + row * DD + seg;
        const __half* s2 = Q2g + row * DD + seg;
#pragma unroll
        for (int j = 0; j < 4; j++) { CP16(d1 + j * 16, s1 + j * 8); CP16(d2 + j * 16, s2 + j * 8); }
    }
    fl_load_kv(sb, 0, 0, tid, K1g, K2g, Vg);
    CP_COMMIT();

    float O1[8][4], O2[8][4];
#pragma unroll
    for (int nb = 0; nb < 8; nb++)
#pragma unroll
        for (int j = 0; j < 4; j++) { O1[nb][j] = 0.f; O2[nb][j] = 0.f; }
    float m1[2] = {-1e30f, -1e30f}, l1[2] = {0.f, 0.f};
    float m2[2] = {-1e30f, -1e30f}, l2[2] = {0.f, 0.f};

    const int row_g0 = q0 + wid * 16 + (lane >> 2);
    const uint32_t a_lane = (uint32_t)((lane & 15) * QS2 + (lane >> 4) * 8) * 2;
    const uint32_t aQ1 = sb + (uint32_t)(FL_Q1 + wid * 16 * QS2) * 2 + a_lane;
    const uint32_t aQ2 = sb + (uint32_t)(FL_Q2 + wid * 16 * QS2) * 2 + a_lane;
    const uint32_t b_lane_b = (uint32_t)((((lane >> 4) & 1) * 8 + (lane & 7)) * QS2 +
                                         ((lane >> 3) & 1) * 8) * 2;

    for (int kt = 0; kt < nkv; kt++) {
        if (kt + 1 < nkv) {
            fl_load_kv(sb, (kt + 1) & 1, kt + 1, tid, K1g, K2g, Vg);
            CP_COMMIT();
            CP_WAIT(1);
        } else {
            CP_WAIT(0);
        }
        __syncthreads();
        const uint32_t st = sb + (uint32_t)(FL_ST0 + (kt & 1) * FL_STAGE) * 2;
        const bool msk = (kt >= nkv - 2);
        fl_stream(aQ1, st,             st + 2 * FL_KV * 2, b_lane_b, kt, msk, row_g0, lane, O1, m1, l1);
        fl_stream(aQ2, st + FL_KV * 2, st + 2 * FL_KV * 2, b_lane_b, kt, msk, row_g0, lane, O2, m2, l2);
        __syncthreads();
    }

    // epilogue: out = O1/l1 - lam*O2/l2, write split-fp16 [hi|lo] into Af
    float lamv = fminf(fmaxf(lam_p[h], 0.f), 1.f);
    float i10 = 1.f / l1[0], i11 = 1.f / l1[1];
    float i20 = lamv / l2[0], i21 = lamv / l2[1];
    const int row0 = q0 + wid * 16 + (lane >> 2);
    const int colb = h * 64 + 2 * (lane & 3);
    size_t rb0 = (size_t)(b * TT + row0) * KW;
    size_t rb1 = (size_t)(b * TT + row0 + 8) * KW;
#pragma unroll
    for (int nb = 0; nb < 8; nb++) {
        int col = colb + nb * 8;
        float x0 = O1[nb][0] * i10 - O2[nb][0] * i20;
        float x1 = O1[nb][1] * i10 - O2[nb][1] * i20;
        float y0 = O1[nb][2] * i11 - O2[nb][2] * i21;
        float y1 = O1[nb][3] * i11 - O2[nb][3] * i21;
        uint32_t hx = packh(x0, x1);
        __half2 hv = *(__half2*)&hx;
        float2 hf = __half22float2(hv);
        uint32_t lx = packh(x0 - hf.x, x1 - hf.y);
        *(uint32_t*)&Af[rb0 + col] = hx;
        *(uint32_t*)&Af[rb0 + 1024 + col] = lx;
        uint32_t hy = packh(y0, y1);
        __half2 hv2 = *(__half2*)&hy;
        float2 hf2 = __half22float2(hv2);
        uint32_t ly = packh(y0 - hf2.x, y1 - hf2.y);
        *(uint32_t*)&Af[rb1 + col] = hy;
        *(uint32_t*)&Af[rb1 + 1024 + col] = ly;
    }
}

// ---------------- launch ----------------
extern "C" void kernel_launch(void* const* d_in, const int* in_sizes, int n_in,
                              void* d_out, int out_size) {
    const float* x    = (const float*)d_in[0];
    const float* Wqkv = (const float*)d_in[2];
    const float* Wout = (const float*)d_in[3];
    const float* lam  = (const float*)d_in[4];
    float* out = (float*)d_out;

    float* qkv = nullptr;
    __half *Af = nullptr, *Bqf = nullptr, *Bof = nullptr;
    __half *Q1f = nullptr, *Q2f = nullptr, *K1f = nullptr, *K2f = nullptr, *Vt = nullptr;
    cudaGetSymbolAddress((void**)&qkv, g_qkv);
    cudaGetSymbolAddress((void**)&Af,  g_Af);
    cudaGetSymbolAddress((void**)&Bqf, g_Bqf);
    cudaGetSymbolAddress((void**)&Bof, g_Bof);
    cudaGetSymbolAddress((void**)&Q1f, g_Q1f);
    cudaGetSymbolAddress((void**)&Q2f, g_Q2f);
    cudaGetSymbolAddress((void**)&K1f, g_K1f);
    cudaGetSymbolAddress((void**)&K2f, g_K2f);
    cudaGetSymbolAddress((void**)&Vt,  g_Vt);

    cudaFuncSetAttribute(gemm_mma, cudaFuncAttributeMaxDynamicSharedMemorySize, GEMM_SMEM);
    cudaFuncSetAttribute(flash_mma, cudaFuncAttributeMaxDynamicSharedMemorySize, FL_SMEM_BYTES);

    // weight + input conversions
    splitT<<<dim3(NQKV / 32, DM / 32), dim3(32, 8)>>>(Wqkv, Bqf, NQKV);
    splitT<<<dim3(DM / 32, DM / 32), dim3(32, 8)>>>(Wout, Bof, DM);
    split_rows<<<(BT * DM + 255) / 256, 256>>>(x, Af, BT * DM);

    // 1) QKV projection (2-combo fp16 HMMA)
    gemm_mma<<<dim3(NQKV / 128, BT / 128), 256, GEMM_SMEM>>>(Af, Bqf, qkv, NQKV);

    // 2) flash operand prep (fp16)
    qkv_split<<<(BB * HH * TT * DD + 255) / 256, 256>>>(qkv, Q1f, Q2f, K1f, K2f);
    v_transpose<<<dim3(TT / 64, BB * HH), 256>>>(qkv, Vt);

    // 3) dual flash attention (fp16 HMMA); writes split-fp16 attn into Af
    flash_mma<<<dim3(TT / 128, HH, BB), 256, FL_SMEM_BYTES>>>(Q1f, Q2f, K1f, K2f, Vt, lam, Af);

    // 4) output projection (2-combo fp16 HMMA)
    gemm_mma<<<dim3(DM / 128, BT / 128), 256, GEMM_SMEM>>>(Af, Bof, out, DM);
}

// round 13
// speedup vs baseline: 1.2358x; 1.2358x over previous
#include <cuda_runtime.h>
#include <cuda_bf16.h>
#include <cuda_fp16.h>
#include <math.h>
#include <cstdint>

// Problem constants
#define BB 2
#define TT 2048
#define DM 1024
#define HH 16
#define DD 64
#define NQKV 5120     // H * 5 * D
#define BT  4096      // B * T
#define KW  2048      // GEMM operands: [hi(1024) | lo(1024)] bf16

// ---------------- scratch (no cudaMalloc allowed) ----------------
__device__ __align__(16) float g_qkv[(size_t)BT * NQKV];               // 83.9 MB
__device__ __align__(16) __nv_bfloat16 g_Ab[(size_t)BT * KW];          // 16.8 MB
__device__ __align__(16) __nv_bfloat16 g_Bq[(size_t)NQKV * KW];        // 21.0 MB
__device__ __align__(16) __nv_bfloat16 g_Bo[(size_t)DM * KW];          // 4.2 MB
// flash operands (fp16 single-plane): [bh][t][64], V^T [bh][d][t]
__device__ __align__(16) __half g_Q1f[(size_t)BB * HH * TT * DD];
__device__ __align__(16) __half g_Q2f[(size_t)BB * HH * TT * DD];
__device__ __align__(16) __half g_K1f[(size_t)BB * HH * TT * DD];
__device__ __align__(16) __half g_K2f[(size_t)BB * HH * TT * DD];
__device__ __align__(16) __half g_Vt [(size_t)BB * HH * DD * TT];

// ================= helpers (plain sm_103-safe PTX only) =================
__device__ __forceinline__ uint32_t smem_u32(const void* p) {
    uint32_t a;
    asm("{ .reg .u64 t; cvta.to.shared.u64 t, %1; cvt.u32.u64 %0, t; }" : "=r"(a) : "l"(p));
    return a;
}
#define CP16(smem, gptr) \
    asm volatile("cp.async.cg.shared.global [%0], [%1], 16;" :: "r"(smem), "l"(gptr) : "memory")
#define CP_COMMIT() asm volatile("cp.async.commit_group;" ::: "memory")
#define CP_WAIT(n)  asm volatile("cp.async.wait_group %0;" :: "n"(n) : "memory")
#define LDSM_X4(r0, r1, r2, r3, addr) \
    asm volatile("ldmatrix.sync.aligned.m8n8.x4.shared.b16 {%0,%1,%2,%3}, [%4];" \
                 : "=r"(r0), "=r"(r1), "=r"(r2), "=r"(r3) : "r"(addr))
#define MMA16816(c, a, b) \
    asm volatile("mma.sync.aligned.m16n8k16.row.col.f32.bf16.bf16.f32 " \
                 "{%0,%1,%2,%3}, {%4,%5,%6,%7}, {%8,%9}, {%0,%1,%2,%3};" \
                 : "+f"((c)[0]), "+f"((c)[1]), "+f"((c)[2]), "+f"((c)[3]) \
                 : "r"((a)[0]), "r"((a)[1]), "r"((a)[2]), "r"((a)[3]), \
                   "r"((b)[0]), "r"((b)[1]))
#define MMAH16816(c, a, b) \
    asm volatile("mma.sync.aligned.m16n8k16.row.col.f32.f16.f16.f32 " \
                 "{%0,%1,%2,%3}, {%4,%5,%6,%7}, {%8,%9}, {%0,%1,%2,%3};" \
                 : "+f"((c)[0]), "+f"((c)[1]), "+f"((c)[2]), "+f"((c)[3]) \
                 : "r"((a)[0]), "r"((a)[1]), "r"((a)[2]), "r"((a)[3]), \
                   "r"((b)[0]), "r"((b)[1]))

__device__ __forceinline__ uint32_t packbf(float lo, float hi) {
    __nv_bfloat162 t = __floats2bfloat162_rn(lo, hi);
    return *(uint32_t*)&t;
}
__device__ __forceinline__ uint32_t packh(float lo, float hi) {
    __half2 t = __floats2half2_rn(lo, hi);
    return *(uint32_t*)&t;
}

// ================= conversion kernels =================
// fp32 [M,1024] row-major -> bf16 [M,2048]: cols [0,1024)=hi [1024,2048)=lo
__global__ void __launch_bounds__(256) split_rows(const float* __restrict__ in,
                                                  __nv_bfloat16* __restrict__ out, int total) {
    int idx = blockIdx.x * 256 + threadIdx.x;
    if (idx >= total) return;
    int m = idx >> 10, k = idx & 1023;
    float v = in[idx];
    __nv_bfloat16 h = __float2bfloat16(v);
    __nv_bfloat16 l = __float2bfloat16(v - __bfloat162float(h));
    size_t rb = (size_t)m * KW;
    out[rb + k] = h;
    out[rb + 1024 + k] = l;
}

// W fp32 [1024, N] -> bf16 [N, 2048] transposed: cols [0,1024)=hi [1024,2048)=lo
__global__ void __launch_bounds__(256) splitT(const float* __restrict__ W,
                                              __nv_bfloat16* __restrict__ out, int N) {
    __shared__ float smt[32][33];
    int n0 = blockIdx.x * 32, k0 = blockIdx.y * 32;
    int tx = threadIdx.x, ty = threadIdx.y;  // 32 x 8
#pragma unroll
    for (int i = 0; i < 4; i++)
        smt[ty * 4 + i][tx] = W[(size_t)(k0 + ty * 4 + i) * N + n0 + tx];
    __syncthreads();
#pragma unroll
    for (int i = 0; i < 4; i++) {
        int nn = ty * 4 + i;
        float v = smt[tx][nn];
        __nv_bfloat16 h = __float2bfloat16(v);
        __nv_bfloat16 l = __float2bfloat16(v - __bfloat162float(h));
        size_t rb = (size_t)(n0 + nn) * KW + k0 + tx;
        out[rb] = h;
        out[rb + 1024] = l;
    }
}

// g_qkv fp32 -> Q1/Q2/K1/K2 fp16 [bh][t][64]
__global__ void __launch_bounds__(256) qkv_split(const float* __restrict__ qkv,
                                                 __half* __restrict__ Q1,
                                                 __half* __restrict__ Q2,
                                                 __half* __restrict__ K1,
                                                 __half* __restrict__ K2) {
    int idx = blockIdx.x * 256 + threadIdx.x;           // over bh*T*64
    if (idx >= BB * HH * TT * DD) return;
    int d = idx & 63;
    int t = (idx >> 6) & (TT - 1);
    int bh = idx >> 17;
    int b = bh >> 4, h = bh & 15;
    const float* src = qkv + (size_t)(b * TT + t) * NQKV + h * 320 + d;
    size_t dst = ((size_t)bh * TT + t) * DD + d;
    Q1[dst] = __float2half(src[0]);
    Q2[dst] = __float2half(src[64]);
    K1[dst] = __float2half(src[128]);
    K2[dst] = __float2half(src[192]);
}

// V fp32 [t, d] -> V^T fp16 [bh][d][t]
__global__ void __launch_bounds__(256) v_transpose(const float* __restrict__ qkv,
                                                   __half* __restrict__ Vt) {
    __shared__ float tile[64][65];
    int t0 = blockIdx.x * 64;
    int bh = blockIdx.y;
    int b = bh >> 4, h = bh & 15;
    int c = threadIdx.x & 63, r4 = threadIdx.x >> 6;
#pragma unroll
    for (int rr = r4; rr < 64; rr += 4)
        tile[rr][c] = qkv[(size_t)(b * TT + t0 + rr) * NQKV + h * 320 + 256 + c];
    __syncthreads();
#pragma unroll
    for (int dd = r4; dd < 64; dd += 4)
        Vt[((size_t)bh * DD + dd) * TT + t0 + c] = __float2half(tile[c][dd]);
}

// ========== HMMA split-bf16 GEMM: C[M,N] = (Ahi+Alo)[M,1024] @ (Bhi+Blo)[N,1024]^T ==========
// 3-combo (hi*hi + hi*lo + lo*hi), 128x128 CTA tile, 8 warps (4m x 2n), warp tile 32x64.
// 3-stage cp.async pipeline + ks-level register-fragment double buffering.
#define BKC 64
#define NKI (1024 / BKC)      // 16
#define ASTR 72               // smem row stride in bf16
#define TILE_E (128 * ASTR)   // one 128x64 tile (padded)
#define STAGE_E (4 * TILE_E)  // Ahi | Alo | Bhi | Blo
#define NSTAGE 3
#define GEMM_SMEM (NSTAGE * STAGE_E * 2)   // 221184 bytes

__global__ void __launch_bounds__(256) gemm_mma(const __nv_bfloat16* __restrict__ A,
                                                const __nv_bfloat16* __restrict__ B,
                                                float* __restrict__ C, int Ntot) {
    extern __shared__ __nv_bfloat16 smb[];
    const int tid = threadIdx.x;
    const int wid = tid >> 5;
    const int lane = tid & 31;
    const int m0 = blockIdx.y * 128;
    const int n0 = blockIdx.x * 128;
    const int wm = (wid >> 1) * 32;
    const int wn = (wid & 1) * 64;
    const uint32_t sbase = smem_u32(smb);

    const int ldrow = tid >> 1;
    const int ldcol = (tid & 1) * 32;
    const __nv_bfloat16* Agp = A + (size_t)(m0 + ldrow) * KW + ldcol;
    const __nv_bfloat16* Bgp = B + (size_t)(n0 + ldrow) * KW + ldcol;
    const uint32_t st_off = (uint32_t)(ldrow * ASTR + ldcol) * 2;

    uint32_t aoff[2], boff[4];
#pragma unroll
    for (int mt = 0; mt < 2; mt++) {
        int row = wm + mt * 16 + (lane & 15);
        int col = (lane >> 4) * 8;
        aoff[mt] = (uint32_t)(row * ASTR + col) * 2;
    }
#pragma unroll
    for (int nt2 = 0; nt2 < 4; nt2++) {
        int n = wn + nt2 * 16 + ((lane >> 4) & 1) * 8 + (lane & 7);
        int k = ((lane >> 3) & 1) * 8;
        boff[nt2] = (uint32_t)(n * ASTR + k) * 2;
    }

    float acc[2][8][4];
#pragma unroll
    for (int mt = 0; mt < 2; mt++)
#pragma unroll
        for (int nt = 0; nt < 8; nt++)
#pragma unroll
            for (int j = 0; j < 4; j++) acc[mt][nt][j] = 0.f;

#define LOAD_STAGE(s, k0)                                                          \
    do {                                                                           \
        uint32_t _b = sbase + (uint32_t)(s) * STAGE_E * 2 + st_off;                \
        const __nv_bfloat16* _a = Agp + (k0);                                      \
        const __nv_bfloat16* _bb = Bgp + (k0);                                     \
        _Pragma("unroll")                                                          \
        for (int j = 0; j < 4; j++) {                                              \
            CP16(_b + j * 16, _a + j * 8);                                         \
            CP16(_b + TILE_E * 2 + j * 16, _a + 1024 + j * 8);                     \
            CP16(_b + 2 * TILE_E * 2 + j * 16, _bb + j * 8);                       \
            CP16(_b + 3 * TILE_E * 2 + j * 16, _bb + 1024 + j * 8);                \
        }                                                                          \
    } while (0)

    // fragment double buffers (ks-level pipeline)
    uint32_t ah[2][2][4], al[2][2][4], bh[2][4][4], bl[2][4][4];

#define LOAD_FRAGS(fb, ks)                                                         \
    do {                                                                           \
        _Pragma("unroll")                                                          \
        for (int mt = 0; mt < 2; mt++) {                                           \
            LDSM_X4(ah[fb][mt][0], ah[fb][mt][1], ah[fb][mt][2], ah[fb][mt][3],    \
                    stAh + aoff[mt] + (ks) * 32);                                  \
            LDSM_X4(al[fb][mt][0], al[fb][mt][1], al[fb][mt][2], al[fb][mt][3],    \
                    stAl + aoff[mt] + (ks) * 32);                                  \
        }                                                                          \
        _Pragma("unroll")                                                          \
        for (int nt2 = 0; nt2 < 4; nt2++) {                                        \
            LDSM_X4(bh[fb][nt2][0], bh[fb][nt2][1], bh[fb][nt2][2], bh[fb][nt2][3],\
                    stBh + boff[nt2] + (ks) * 32);                                 \
            LDSM_X4(bl[fb][nt2][0], bl[fb][nt2][1], bl[fb][nt2][2], bl[fb][nt2][3],\
                    stBl + boff[nt2] + (ks) * 32);                                 \
        }                                                                          \
    } while (0)

    LOAD_STAGE(0, 0);
    CP_COMMIT();
    LOAD_STAGE(1, BKC);
    CP_COMMIT();

    for (int i = 0; i < NKI; i++) {
        if (i + 1 < NKI) { CP_WAIT(1); } else { CP_WAIT(0); }
        __syncthreads();
        if (i + 2 < NKI) {
            LOAD_STAGE((i + 2) % NSTAGE, (i + 2) * BKC);
            CP_COMMIT();
        }
        const uint32_t stAh = sbase + (uint32_t)(i % NSTAGE) * STAGE_E * 2;
        const uint32_t stAl = stAh + TILE_E * 2;
        const uint32_t stBh = stAh + 2 * TILE_E * 2;
        const uint32_t stBl = stAh + 3 * TILE_E * 2;

        LOAD_FRAGS(0, 0);
#pragma unroll
        for (int ks = 0; ks < 4; ks++) {
            const int cur = ks & 1;
            if (ks < 3) LOAD_FRAGS(cur ^ 1, ks + 1);
#pragma unroll
            for (int mt = 0; mt < 2; mt++)
#pragma unroll
                for (int nt2 = 0; nt2 < 4; nt2++) {
                    MMA16816(acc[mt][2 * nt2],     ah[cur][mt], (&bh[cur][nt2][0]));
                    MMA16816(acc[mt][2 * nt2 + 1], ah[cur][mt], (&bh[cur][nt2][2]));
                    MMA16816(acc[mt][2 * nt2],     ah[cur][mt], (&bl[cur][nt2][0]));
                    MMA16816(acc[mt][2 * nt2 + 1], ah[cur][mt], (&bl[cur][nt2][2]));
                    MMA16816(acc[mt][2 * nt2],     al[cur][mt], (&bh[cur][nt2][0]));
                    MMA16816(acc[mt][2 * nt2 + 1], al[cur][mt], (&bh[cur][nt2][2]));
                }
        }
    }
#undef LOAD_STAGE
#undef LOAD_FRAGS

#pragma unroll
    for (int mt = 0; mt < 2; mt++) {
        int r0 = m0 + wm + mt * 16 + (lane >> 2);
        int c0 = n0 + wn + (lane & 3) * 2;
        float* p0 = C + (size_t)r0 * Ntot + c0;
        float* p1 = C + (size_t)(r0 + 8) * Ntot + c0;
#pragma unroll
        for (int nt = 0; nt < 8; nt++) {
            *(float2*)(p0 + nt * 8) = make_float2(acc[mt][nt][0], acc[mt][nt][1]);
            *(float2*)(p1 + nt * 8) = make_float2(acc[mt][nt][2], acc[mt][nt][3]);
        }
    }
}

// ================= fp16 HMMA dual flash attention =================
// CTA: 128 q-rows of one (b,h); 8 warps, warp = m16. kv tiles of 64, double-buffered.
#define QS2 72                        // fp16 row stride (144B)
#define FL_Q1 0
#define FL_Q2 (128 * QS2)
#define FL_ST0 (2 * 128 * QS2)
#define FL_KV (64 * QS2)              // one tensor in a stage
#define FL_STAGE (3 * FL_KV)          // K1 | K2 | Vt
#define FL_SMEM_BYTES ((2 * 128 * QS2 + 2 * FL_STAGE) * 2)   // 92160

__device__ __forceinline__ void fl_load_kv(uint32_t sb, int st, int kt, int tid,
                                           const __half* K1g,
                                           const __half* K2g,
                                           const __half* Vg) {
    int r = tid >> 2, qd = tid & 3;   // row 0..63, 16-elem quarter
    uint32_t base = sb + (uint32_t)(FL_ST0 + st * FL_STAGE) * 2;
    uint32_t o = (uint32_t)(r * QS2 + qd * 16) * 2;
    const __half* k1 = K1g + (size_t)(kt * 64 + r) * DD + qd * 16;
    const __half* k2 = K2g + (size_t)(kt * 64 + r) * DD + qd * 16;
    const __half* vv = Vg + (size_t)r * TT + kt * 64 + qd * 16;
#pragma unroll
    for (int j = 0; j < 2; j++) {
        CP16(base + o + j * 16, k1 + j * 8);
        CP16(base + FL_KV * 2 + o + j * 16, k2 + j * 8);
        CP16(base + 2 * FL_KV * 2 + o + j * 16, vv + j * 8);
    }
}

// one stream: S = Q K^T (fp16), online softmax, O += P V (fp16)
__device__ __forceinline__ void fl_stream(uint32_t a_addr, uint32_t kstage, uint32_t vstage,
                                          uint32_t b_lane_b, int kt, bool need_mask,
                                          int row_g0, int lane,
                                          float O[8][4], float* mst, float* lst) {
    float acc[8][4];
#pragma unroll
    for (int nb = 0; nb < 8; nb++)
#pragma unroll
        for (int j = 0; j < 4; j++) acc[nb][j] = 0.f;

    // S = Q K^T, 4 k16 steps over D=64
#pragma unroll
    for (int s = 0; s < 4; s++) {
        uint32_t af[4];
        LDSM_X4(af[0], af[1], af[2], af[3], a_addr + s * 32);
#pragma unroll
        for (int nt2 = 0; nt2 < 4; nt2++) {
            uint32_t bf[4];
            LDSM_X4(bf[0], bf[1], bf[2], bf[3],
                    kstage + b_lane_b + (uint32_t)(nt2 * 16 * QS2 + s * 16) * 2);
            MMAH16816(acc[2 * nt2],     af, (&bf[0]));
            MMAH16816(acc[2 * nt2 + 1], af, (&bf[2]));
        }
    }

    // scale + causal mask
#pragma unroll
    for (int nb = 0; nb < 8; nb++)
#pragma unroll
        for (int j = 0; j < 4; j++) {
            float v = acc[nb][j] * 0.125f;
            if (need_mask) {
                int col = kt * 64 + nb * 8 + 2 * (lane & 3) + (j & 1);
                int row = row_g0 + ((j >> 1) << 3);
                if (col > row) v = -1e30f;
            }
            acc[nb][j] = v;
        }

    // online softmax (rows r and r+8)
    float mx0 = -1e30f, mx1 = -1e30f;
#pragma unroll
    for (int nb = 0; nb < 8; nb++) {
        mx0 = fmaxf(mx0, fmaxf(acc[nb][0], acc[nb][1]));
        mx1 = fmaxf(mx1, fmaxf(acc[nb][2], acc[nb][3]));
    }
    mx0 = fmaxf(mx0, __shfl_xor_sync(0xffffffffu, mx0, 1));
    mx0 = fmaxf(mx0, __shfl_xor_sync(0xffffffffu, mx0, 2));
    mx1 = fmaxf(mx1, __shfl_xor_sync(0xffffffffu, mx1, 1));
    mx1 = fmaxf(mx1, __shfl_xor_sync(0xffffffffu, mx1, 2));
    float mn0 = fmaxf(mst[0], mx0), mn1 = fmaxf(mst[1], mx1);
    float al0 = __expf(mst[0] - mn0), al1 = __expf(mst[1] - mn1);
    float s0 = 0.f, s1 = 0.f;
#pragma unroll
    for (int nb = 0; nb < 8; nb++) {
        acc[nb][0] = __expf(acc[nb][0] - mn0);
        acc[nb][1] = __expf(acc[nb][1] - mn0);
        acc[nb][2] = __expf(acc[nb][2] - mn1);
        acc[nb][3] = __expf(acc[nb][3] - mn1);
        s0 += acc[nb][0] + acc[nb][1];
        s1 += acc[nb][2] + acc[nb][3];
    }
    s0 += __shfl_xor_sync(0xffffffffu, s0, 1);
    s0 += __shfl_xor_sync(0xffffffffu, s0, 2);
    s1 += __shfl_xor_sync(0xffffffffu, s1, 1);
    s1 += __shfl_xor_sync(0xffffffffu, s1, 2);
    lst[0] = lst[0] * al0 + s0;
    lst[1] = lst[1] * al1 + s1;
    mst[0] = mn0;
    mst[1] = mn1;
#pragma unroll
    for (int nb = 0; nb < 8; nb++) {
        O[nb][0] *= al0; O[nb][1] *= al0;
        O[nb][2] *= al1; O[nb][3] *= al1;
    }

    // O += P V (register-direct fp16 P fragments)
#pragma unroll
    for (int s = 0; s < 4; s++) {
        uint32_t ah[4];
        ah[0] = packh(acc[2 * s][0],     acc[2 * s][1]);
        ah[1] = packh(acc[2 * s][2],     acc[2 * s][3]);
        ah[2] = packh(acc[2 * s + 1][0], acc[2 * s + 1][1]);
        ah[3] = packh(acc[2 * s + 1][2], acc[2 * s + 1][3]);
#pragma unroll
        for (int nt2 = 0; nt2 < 4; nt2++) {
            uint32_t bv[4];
            LDSM_X4(bv[0], bv[1], bv[2], bv[3],
                    vstage + b_lane_b + (uint32_t)(nt2 * 16 * QS2 + s * 16) * 2);
            MMAH16816(O[2 * nt2],     ah, (&bv[0]));
            MMAH16816(O[2 * nt2 + 1], ah, (&bv[2]));
        }
    }
}

__global__ void __launch_bounds__(256) flash_mma(
    const __half* __restrict__ Q1f, const __half* __restrict__ Q2f,
    const __half* __restrict__ K1f, const __half* __restrict__ K2f,
    const __half* __restrict__ Vtg, const float* __restrict__ lam_p,
    __nv_bfloat16* __restrict__ Ab) {
    extern __shared__ __half sfb[];
    const uint32_t sb = smem_u32(sfb);
    const int tid = threadIdx.x, wid = tid >> 5, lane = tid & 31;
    const int qrev = gridDim.x - 1 - blockIdx.x;    // heavy CTAs first
    const int q0 = qrev * 128;
    const int h = blockIdx.y, b = blockIdx.z;
    const int bh = b * HH + h;
    const int nkv = 2 * qrev + 2;

    const __half* Q1g = Q1f + ((size_t)bh * TT + q0) * DD;
    const __half* Q2g = Q2f + ((size_t)bh * TT + q0) * DD;
    const __half* K1g = K1f + (size_t)bh * TT * DD;
    const __half* K2g = K2f + (size_t)bh * TT * DD;
    const __half* Vg  = Vtg + (size_t)bh * DD * TT;

    // Q tiles via cp.async: 128 rows x 64 fp16
    {
        int row = tid >> 1, seg = (tid & 1) * 32;
        uint32_t d1 = sb + (uint32_t)(FL_Q1 + row * QS2 + seg) * 2;
        uint32_t d2 = sb + (uint32_t)(FL_Q2 + row * QS2 + seg) * 2;
        const __half* s1 = Q1g + row * DD + seg;
        const __half* s2 = Q2g + row * DD + seg;
#pragma unroll
        for (int j = 0; j < 4; j++) { CP16(d1 + j * 16, s1 + j * 8); CP16(d2 + j * 16, s2 + j * 8); }
    }
    fl_load_kv(sb, 0, 0, tid, K1g, K2g, Vg);
    CP_COMMIT();

    float O1[8][4], O2[8][4];
#pragma unroll
    for (int nb = 0; nb < 8; nb++)
#pragma unroll
        for (int j = 0; j < 4; j++) { O1[nb][j] = 0.f; O2[nb][j] = 0.f; }
    float m1[2] = {-1e30f, -1e30f}, l1[2] = {0.f, 0.f};
    float m2[2] = {-1e30f, -1e30f}, l2[2] = {0.f, 0.f};

    const int row_g0 = q0 + wid * 16 + (lane >> 2);
    const uint32_t a_lane = (uint32_t)((lane & 15) * QS2 + (lane >> 4) * 8) * 2;
    const uint32_t aQ1 = sb + (uint32_t)(FL_Q1 + wid * 16 * QS2) * 2 + a_lane;
    const uint32_t aQ2 = sb + (uint32_t)(FL_Q2 + wid * 16 * QS2) * 2 + a_lane;
    const uint32_t b_lane_b = (uint32_t)((((lane >> 4) & 1) * 8 + (lane & 7)) * QS2 +
                                         ((lane >> 3) & 1) * 8) * 2;

    for (int kt = 0; kt < nkv; kt++) {
        if (kt + 1 < nkv) {
            fl_load_kv(sb, (kt + 1) & 1, kt + 1, tid, K1g, K2g, Vg);
            CP_COMMIT();
            CP_WAIT(1);
        } else {
            CP_WAIT(0);
        }
        __syncthreads();
        const uint32_t st = sb + (uint32_t)(FL_ST0 + (kt & 1) * FL_STAGE) * 2;
        const bool msk = (kt >= nkv - 2);
        fl_stream(aQ1, st,             st + 2 * FL_KV * 2, b_lane_b, kt, msk, row_g0, lane, O1, m1, l1);
        fl_stream(aQ2, st + FL_KV * 2, st + 2 * FL_KV * 2, b_lane_b, kt, msk, row_g0, lane, O2, m2, l2);
        __syncthreads();
    }

    // epilogue: out = O1/l1 - lam*O2/l2, write split-bf16 [hi|lo] into Ab
    float lamv = fminf(fmaxf(lam_p[h], 0.f), 1.f);
    float i10 = 1.f / l1[0], i11 = 1.f / l1[1];
    float i20 = lamv / l2[0], i21 = lamv / l2[1];
    const int row0 = q0 + wid * 16 + (lane >> 2);
    const int colb = h * 64 + 2 * (lane & 3);
    size_t rb0 = (size_t)(b * TT + row0) * KW;
    size_t rb1 = (size_t)(b * TT + row0 + 8) * KW;
#pragma unroll
    for (int nb = 0; nb < 8; nb++) {
        int col = colb + nb * 8;
        float x0 = O1[nb][0] * i10 - O2[nb][0] * i20;
        float x1 = O1[nb][1] * i10 - O2[nb][1] * i20;
        float y0 = O1[nb][2] * i11 - O2[nb][2] * i21;
        float y1 = O1[nb][3] * i11 - O2[nb][3] * i21;
        uint32_t hx = packbf(x0, x1);
        __nv_bfloat162 hv = *(__nv_bfloat162*)&hx;
        float2 hf = __bfloat1622float2(hv);
        uint32_t lx = packbf(x0 - hf.x, x1 - hf.y);
        *(uint32_t*)&Ab[rb0 + col] = hx;
        *(uint32_t*)&Ab[rb0 + 1024 + col] = lx;
        uint32_t hy = packbf(y0, y1);
        __nv_bfloat162 hv2 = *(__nv_bfloat162*)&hy;
        float2 hf2 = __bfloat1622float2(hv2);
        uint32_t ly = packbf(y0 - hf2.x, y1 - hf2.y);
        *(uint32_t*)&Ab[rb1 + col] = hy;
        *(uint32_t*)&Ab[rb1 + 1024 + col] = ly;
    }
}

// ---------------- launch ----------------
extern "C" void kernel_launch(void* const* d_in, const int* in_sizes, int n_in,
                              void* d_out, int out_size) {
    const float* x    = (const float*)d_in[0];
    const float* Wqkv = (const float*)d_in[2];
    const float* Wout = (const float*)d_in[3];
    const float* lam  = (const float*)d_in[4];
    float* out = (float*)d_out;

    float* qkv = nullptr;
    __nv_bfloat16 *Ab = nullptr, *Bq = nullptr, *Bo = nullptr;
    __half *Q1f = nullptr, *Q2f = nullptr, *K1f = nullptr, *K2f = nullptr, *Vt = nullptr;
    cudaGetSymbolAddress((void**)&qkv, g_qkv);
    cudaGetSymbolAddress((void**)&Ab,  g_Ab);
    cudaGetSymbolAddress((void**)&Bq,  g_Bq);
    cudaGetSymbolAddress((void**)&Bo,  g_Bo);
    cudaGetSymbolAddress((void**)&Q1f, g_Q1f);
    cudaGetSymbolAddress((void**)&Q2f, g_Q2f);
    cudaGetSymbolAddress((void**)&K1f, g_K1f);
    cudaGetSymbolAddress((void**)&K2f, g_K2f);
    cudaGetSymbolAddress((void**)&Vt,  g_Vt);

    cudaFuncSetAttribute(gemm_mma, cudaFuncAttributeMaxDynamicSharedMemorySize, GEMM_SMEM);
    cudaFuncSetAttribute(flash_mma, cudaFuncAttributeMaxDynamicSharedMemorySize, FL_SMEM_BYTES);

    // weight + input split conversions
    splitT<<<dim3(NQKV / 32, DM / 32), dim3(32, 8)>>>(Wqkv, Bq, NQKV);
    splitT<<<dim3(DM / 32, DM / 32), dim3(32, 8)>>>(Wout, Bo, DM);
    split_rows<<<(BT * DM + 255) / 256, 256>>>(x, Ab, BT * DM);

    // 1) QKV projection (bf16 3-combo HMMA, fragment-pipelined)
    gemm_mma<<<dim3(NQKV / 128, BT / 128), 256, GEMM_SMEM>>>(Ab, Bq, qkv, NQKV);

    // 2) flash operand prep (fp16)
    qkv_split<<<(BB * HH * TT * DD + 255) / 256, 256>>>(qkv, Q1f, Q2f, K1f, K2f);
    v_transpose<<<dim3(TT / 64, BB * HH), 256>>>(qkv, Vt);

    // 3) dual flash attention (fp16 HMMA); writes split-bf16 attn into Ab
    flash_mma<<<dim3(TT / 128, HH, BB), 256, FL_SMEM_BYTES>>>(Q1f, Q2f, K1f, K2f, Vt, lam, Ab);

    // 4) output projection (bf16 3-combo HMMA, fragment-pipelined)
    gemm_mma<<<dim3(DM / 128, BT / 128), 256, GEMM_SMEM>>>(Ab, Bo, out, DM);
}

// round 14
// speedup vs baseline: 1.2759x; 1.0325x over previous
#include <cuda_runtime.h>
#include <cuda_bf16.h>
#include <cuda_fp16.h>
#include <math.h>
#include <cstdint>

// Problem constants
#define BB 2
#define TT 2048
#define DM 1024
#define HH 16
#define DD 64
#define NQKV 5120     // H * 5 * D
#define BT  4096      // B * T
#define KW  2048      // GEMM operands: [hi(1024) | lo(1024)] bf16

// ---------------- scratch (no cudaMalloc allowed) ----------------
__device__ __align__(16) __nv_bfloat16 g_Ab[(size_t)BT * KW];          // 16.8 MB
__device__ __align__(16) __nv_bfloat16 g_Bq[(size_t)NQKV * KW];        // 21.0 MB
__device__ __align__(16) __nv_bfloat16 g_Bo[(size_t)DM * KW];          // 4.2 MB
// flash operands (fp16 single-plane): [bh][t][64], V^T [bh][d][t]
__device__ __align__(16) __half g_Q1f[(size_t)BB * HH * TT * DD];
__device__ __align__(16) __half g_Q2f[(size_t)BB * HH * TT * DD];
__device__ __align__(16) __half g_K1f[(size_t)BB * HH * TT * DD];
__device__ __align__(16) __half g_K2f[(size_t)BB * HH * TT * DD];
__device__ __align__(16) __half g_Vh [(size_t)BB * HH * TT * DD];      // V row-major fp16
__device__ __align__(16) __half g_Vt [(size_t)BB * HH * DD * TT];      // V^T

// ================= helpers (plain sm_103-safe PTX only) =================
__device__ __forceinline__ uint32_t smem_u32(const void* p) {
    uint32_t a;
    asm("{ .reg .u64 t; cvta.to.shared.u64 t, %1; cvt.u32.u64 %0, t; }" : "=r"(a) : "l"(p));
    return a;
}
#define CP16(smem, gptr) \
    asm volatile("cp.async.cg.shared.global [%0], [%1], 16;" :: "r"(smem), "l"(gptr) : "memory")
#define CP_COMMIT() asm volatile("cp.async.commit_group;" ::: "memory")
#define CP_WAIT(n)  asm volatile("cp.async.wait_group %0;" :: "n"(n) : "memory")
#define LDSM_X4(r0, r1, r2, r3, addr) \
    asm volatile("ldmatrix.sync.aligned.m8n8.x4.shared.b16 {%0,%1,%2,%3}, [%4];" \
                 : "=r"(r0), "=r"(r1), "=r"(r2), "=r"(r3) : "r"(addr))
#define MMA16816(c, a, b) \
    asm volatile("mma.sync.aligned.m16n8k16.row.col.f32.bf16.bf16.f32 " \
                 "{%0,%1,%2,%3}, {%4,%5,%6,%7}, {%8,%9}, {%0,%1,%2,%3};" \
                 : "+f"((c)[0]), "+f"((c)[1]), "+f"((c)[2]), "+f"((c)[3]) \
                 : "r"((a)[0]), "r"((a)[1]), "r"((a)[2]), "r"((a)[3]), \
                   "r"((b)[0]), "r"((b)[1]))
#define MMAH16816(c, a, b) \
    asm volatile("mma.sync.aligned.m16n8k16.row.col.f32.f16.f16.f32 " \
                 "{%0,%1,%2,%3}, {%4,%5,%6,%7}, {%8,%9}, {%0,%1,%2,%3};" \
                 : "+f"((c)[0]), "+f"((c)[1]), "+f"((c)[2]), "+f"((c)[3]) \
                 : "r"((a)[0]), "r"((a)[1]), "r"((a)[2]), "r"((a)[3]), \
                   "r"((b)[0]), "r"((b)[1]))

__device__ __forceinline__ uint32_t packbf(float lo, float hi) {
    __nv_bfloat162 t = __floats2bfloat162_rn(lo, hi);
    return *(uint32_t*)&t;
}
__device__ __forceinline__ uint32_t packh(float lo, float hi) {
    __half2 t = __floats2half2_rn(lo, hi);
    return *(uint32_t*)&t;
}

// ================= conversion kernels =================
// fp32 [M,1024] row-major -> bf16 [M,2048]: cols [0,1024)=hi [1024,2048)=lo
__global__ void __launch_bounds__(256) split_rows(const float* __restrict__ in,
                                                  __nv_bfloat16* __restrict__ out, int total) {
    int idx = blockIdx.x * 256 + threadIdx.x;
    if (idx >= total) return;
    int m = idx >> 10, k = idx & 1023;
    float v = in[idx];
    __nv_bfloat16 h = __float2bfloat16(v);
    __nv_bfloat16 l = __float2bfloat16(v - __bfloat162float(h));
    size_t rb = (size_t)m * KW;
    out[rb + k] = h;
    out[rb + 1024 + k] = l;
}

// W fp32 [1024, N] -> bf16 [N, 2048] transposed: cols [0,1024)=hi [1024,2048)=lo
__global__ void __launch_bounds__(256) splitT(const float* __restrict__ W,
                                              __nv_bfloat16* __restrict__ out, int N) {
    __shared__ float smt[32][33];
    int n0 = blockIdx.x * 32, k0 = blockIdx.y * 32;
    int tx = threadIdx.x, ty = threadIdx.y;  // 32 x 8
#pragma unroll
    for (int i = 0; i < 4; i++)
        smt[ty * 4 + i][tx] = W[(size_t)(k0 + ty * 4 + i) * N + n0 + tx];
    __syncthreads();
#pragma unroll
    for (int i = 0; i < 4; i++) {
        int nn = ty * 4 + i;
        float v = smt[tx][nn];
        __nv_bfloat16 h = __float2bfloat16(v);
        __nv_bfloat16 l = __float2bfloat16(v - __bfloat162float(h));
        size_t rb = (size_t)(n0 + nn) * KW + k0 + tx;
        out[rb] = h;
        out[rb + 1024] = l;
    }
}

// V fp16 [bh][t][64] -> V^T fp16 [bh][d][t]
__global__ void __launch_bounds__(256) v_transpose_h(const __half* __restrict__ Vh,
                                                     __half* __restrict__ Vt) {
    __shared__ __half tile[64][72];
    int t0 = blockIdx.x * 64;
    int bh = blockIdx.y;
    int c = threadIdx.x & 63, r4 = threadIdx.x >> 6;
#pragma unroll
    for (int rr = r4; rr < 64; rr += 4)
        tile[rr][c] = Vh[((size_t)bh * TT + t0 + rr) * DD + c];
    __syncthreads();
#pragma unroll
    for (int dd = r4; dd < 64; dd += 4)
        Vt[((size_t)bh * DD + dd) * TT + t0 + c] = tile[c][dd];
}

// ========== HMMA split-bf16 GEMM: C[M,N] = (Ahi+Alo)[M,1024] @ (Bhi+Blo)[N,1024]^T ==========
// 3-combo (hi*hi + hi*lo + lo*hi), 128x128 CTA tile, 8 warps (4m x 2n), warp tile 32x64.
// 3-stage cp.async pipeline; COMBO-OUTER MMA order (16 independent accs per combo).
// MODE 0: write fp32 C. MODE 1: fan out fp16 q1/q2/k1/k2/v flash operands.
#define BKC 64
#define NKI (1024 / BKC)      // 16
#define ASTR 72               // smem row stride in bf16
#define TILE_E (128 * ASTR)   // one 128x64 tile (padded)
#define STAGE_E (4 * TILE_E)  // Ahi | Alo | Bhi | Blo
#define NSTAGE 3
#define GEMM_SMEM (NSTAGE * STAGE_E * 2)   // 221184 bytes

template <int MODE>
__global__ void __launch_bounds__(256) gemm_mma(const __nv_bfloat16* __restrict__ A,
                                                const __nv_bfloat16* __restrict__ B,
                                                float* __restrict__ C, int Ntot,
                                                __half* __restrict__ Q1, __half* __restrict__ Q2,
                                                __half* __restrict__ K1, __half* __restrict__ K2,
                                                __half* __restrict__ Vh) {
    extern __shared__ __nv_bfloat16 smb[];
    const int tid = threadIdx.x;
    const int wid = tid >> 5;
    const int lane = tid & 31;
    const int m0 = blockIdx.y * 128;
    const int n0 = blockIdx.x * 128;
    const int wm = (wid >> 1) * 32;
    const int wn = (wid & 1) * 64;
    const uint32_t sbase = smem_u32(smb);

    const int ldrow = tid >> 1;
    const int ldcol = (tid & 1) * 32;
    const __nv_bfloat16* Agp = A + (size_t)(m0 + ldrow) * KW + ldcol;
    const __nv_bfloat16* Bgp = B + (size_t)(n0 + ldrow) * KW + ldcol;
    const uint32_t st_off = (uint32_t)(ldrow * ASTR + ldcol) * 2;

    uint32_t aoff[2], boff[4];
#pragma unroll
    for (int mt = 0; mt < 2; mt++) {
        int row = wm + mt * 16 + (lane & 15);
        int col = (lane >> 4) * 8;
        aoff[mt] = (uint32_t)(row * ASTR + col) * 2;
    }
#pragma unroll
    for (int nt2 = 0; nt2 < 4; nt2++) {
        int n = wn + nt2 * 16 + ((lane >> 4) & 1) * 8 + (lane & 7);
        int k = ((lane >> 3) & 1) * 8;
        boff[nt2] = (uint32_t)(n * ASTR + k) * 2;
    }

    float acc[2][8][4];
#pragma unroll
    for (int mt = 0; mt < 2; mt++)
#pragma unroll
        for (int nt = 0; nt < 8; nt++)
#pragma unroll
            for (int j = 0; j < 4; j++) acc[mt][nt][j] = 0.f;

#define LOAD_STAGE(s, k0)                                                          \
    do {                                                                           \
        uint32_t _b = sbase + (uint32_t)(s) * STAGE_E * 2 + st_off;                \
        const __nv_bfloat16* _a = Agp + (k0);                                      \
        const __nv_bfloat16* _bb = Bgp + (k0);                                     \
        _Pragma("unroll")                                                          \
        for (int j = 0; j < 4; j++) {                                              \
            CP16(_b + j * 16, _a + j * 8);                                         \
            CP16(_b + TILE_E * 2 + j * 16, _a + 1024 + j * 8);                     \
            CP16(_b + 2 * TILE_E * 2 + j * 16, _bb + j * 8);                       \
            CP16(_b + 3 * TILE_E * 2 + j * 16, _bb + 1024 + j * 8);                \
        }                                                                          \
    } while (0)

    // one combo = 16 MMAs into 16 independent accumulators
#define COMBO(afr, bfr)                                                            \
    do {                                                                           \
        _Pragma("unroll")                                                          \
        for (int mt = 0; mt < 2; mt++)                                             \
            _Pragma("unroll")                                                      \
            for (int nt2 = 0; nt2 < 4; nt2++) {                                    \
                MMA16816(acc[mt][2 * nt2],     (afr)[mt], (&(bfr)[nt2][0]));       \
                MMA16816(acc[mt][2 * nt2 + 1], (afr)[mt], (&(bfr)[nt2][2]));       \
            }                                                                      \
    } while (0)

    LOAD_STAGE(0, 0);
    CP_COMMIT();
    LOAD_STAGE(1, BKC);
    CP_COMMIT();

    for (int i = 0; i < NKI; i++) {
        if (i + 1 < NKI) { CP_WAIT(1); } else { CP_WAIT(0); }
        __syncthreads();
        if (i + 2 < NKI) {
            LOAD_STAGE((i + 2) % NSTAGE, (i + 2) * BKC);
            CP_COMMIT();
        }
        const uint32_t stAh = sbase + (uint32_t)(i % NSTAGE) * STAGE_E * 2;
        const uint32_t stAl = stAh + TILE_E * 2;
        const uint32_t stBh = stAh + 2 * TILE_E * 2;
        const uint32_t stBl = stAh + 3 * TILE_E * 2;
#pragma unroll
        for (int ks = 0; ks < 4; ks++) {
            uint32_t ah[2][4], al[2][4], bh[4][4], bl[4][4];
#pragma unroll
            for (int mt = 0; mt < 2; mt++) {
                LDSM_X4(ah[mt][0], ah[mt][1], ah[mt][2], ah[mt][3], stAh + aoff[mt] + ks * 32);
                LDSM_X4(al[mt][0], al[mt][1], al[mt][2], al[mt][3], stAl + aoff[mt] + ks * 32);
            }
#pragma unroll
            for (int nt2 = 0; nt2 < 4; nt2++) {
                LDSM_X4(bh[nt2][0], bh[nt2][1], bh[nt2][2], bh[nt2][3], stBh + boff[nt2] + ks * 32);
                LDSM_X4(bl[nt2][0], bl[nt2][1], bl[nt2][2], bl[nt2][3], stBl + boff[nt2] + ks * 32);
            }
            // combo-outer: dependent accumulator reuse distance = 15 instructions
            COMBO(ah, bh);
            COMBO(ah, bl);
            COMBO(al, bh);
        }
    }
#undef LOAD_STAGE
#undef COMBO

    if (MODE == 0) {
        // fp32 C epilogue
#pragma unroll
        for (int mt = 0; mt < 2; mt++) {
            int r0 = m0 + wm + mt * 16 + (lane >> 2);
            int c0 = n0 + wn + (lane & 3) * 2;
            float* p0 = C + (size_t)r0 * Ntot + c0;
            float* p1 = C + (size_t)(r0 + 8) * Ntot + c0;
#pragma unroll
            for (int nt = 0; nt < 8; nt++) {
                *(float2*)(p0 + nt * 8) = make_float2(acc[mt][nt][0], acc[mt][nt][1]);
                *(float2*)(p1 + nt * 8) = make_float2(acc[mt][nt][2], acc[mt][nt][3]);
            }
        }
    } else {
        // QKV fan-out epilogue: this warp's 64 columns = one 64-col segment
        const int seg = (n0 + wn) >> 6;     // 0..79
        const int hd  = seg / 5;
        const int part = seg % 5;
        __half* dst = (part == 0) ? Q1 : (part == 1) ? Q2 : (part == 2) ? K1
                     : (part == 3) ? K2 : Vh;
        const int dcol = (lane & 3) * 2;
#pragma unroll
        for (int mt = 0; mt < 2; mt++) {
            int r0 = m0 + wm + mt * 16 + (lane >> 2);
#pragma unroll
            for (int half = 0; half < 2; half++) {
                int row = r0 + half * 8;
                int b = row >> 11, t = row & (TT - 1);
                size_t base = ((size_t)(b * HH + hd) * TT + t) * DD + dcol;
#pragma unroll
                for (int nt = 0; nt < 8; nt++) {
                    uint32_t hv = packh(acc[mt][nt][2 * half], acc[mt][nt][2 * half + 1]);
                    *(uint32_t*)&dst[base + nt * 8] = hv;
                }
            }
        }
    }
}

// ================= fp16 HMMA dual flash attention =================
// CTA: 128 q-rows of one (b,h); 8 warps, warp = m16. kv tiles of 64, double-buffered.
#define QS2 72                        // fp16 row stride (144B)
#define FL_Q1 0
#define FL_Q2 (128 * QS2)
#define FL_ST0 (2 * 128 * QS2)
#define FL_KV (64 * QS2)              // one tensor in a stage
#define FL_STAGE (3 * FL_KV)          // K1 | K2 | Vt
#define FL_SMEM_BYTES ((2 * 128 * QS2 + 2 * FL_STAGE) * 2)   // 92160

__device__ __forceinline__ void fl_load_kv(uint32_t sb, int st, int kt, int tid,
                                           const __half* K1g,
                                           const __half* K2g,
                                           const __half* Vg) {
    int r = tid >> 2, qd = tid & 3;   // row 0..63, 16-elem quarter
    uint32_t base = sb + (uint32_t)(FL_ST0 + st * FL_STAGE) * 2;
    uint32_t o = (uint32_t)(r * QS2 + qd * 16) * 2;
    const __half* k1 = K1g + (size_t)(kt * 64 + r) * DD + qd * 16;
    const __half* k2 = K2g + (size_t)(kt * 64 + r) * DD + qd * 16;
    const __half* vv = Vg + (size_t)r * TT + kt * 64 + qd * 16;
#pragma unroll
    for (int j = 0; j < 2; j++) {
        CP16(base + o + j * 16, k1 + j * 8);
        CP16(base + FL_KV * 2 + o + j * 16, k2 + j * 8);
        CP16(base + 2 * FL_KV * 2 + o + j * 16, vv + j * 8);
    }
}

// one stream: S = Q K^T (fp16), online softmax, O += P V (fp16)
__device__ __forceinline__ void fl_stream(uint32_t a_addr, uint32_t kstage, uint32_t vstage,
                                          uint32_t b_lane_b, int kt, bool need_mask,
                                          int row_g0, int lane,
                                          float O[8][4], float* mst, float* lst) {
    float acc[8][4];
#pragma unroll
    for (int nb = 0; nb < 8; nb++)
#pragma unroll
        for (int j = 0; j < 4; j++) acc[nb][j] = 0.f;

    // S = Q K^T, 4 k16 steps over D=64
#pragma unroll
    for (int s = 0; s < 4; s++) {
        uint32_t af[4];
        LDSM_X4(af[0], af[1], af[2], af[3], a_addr + s * 32);
#pragma unroll
        for (int nt2 = 0; nt2 < 4; nt2++) {
            uint32_t bf[4];
            LDSM_X4(bf[0], bf[1], bf[2], bf[3],
                    kstage + b_lane_b + (uint32_t)(nt2 * 16 * QS2 + s * 16) * 2);
            MMAH16816(acc[2 * nt2],     af, (&bf[0]));
            MMAH16816(acc[2 * nt2 + 1], af, (&bf[2]));
        }
    }

    // scale + causal mask
#pragma unroll
    for (int nb = 0; nb < 8; nb++)
#pragma unroll
        for (int j = 0; j < 4; j++) {
            float v = acc[nb][j] * 0.125f;
            if (need_mask) {
                int col = kt * 64 + nb * 8 + 2 * (lane & 3) + (j & 1);
                int row = row_g0 + ((j >> 1) << 3);
                if (col > row) v = -1e30f;
            }
            acc[nb][j] = v;
        }

    // online softmax (rows r and r+8)
    float mx0 = -1e30f, mx1 = -1e30f;
#pragma unroll
    for (int nb = 0; nb < 8; nb++) {
        mx0 = fmaxf(mx0, fmaxf(acc[nb][0], acc[nb][1]));
        mx1 = fmaxf(mx1, fmaxf(acc[nb][2], acc[nb][3]));
    }
    mx0 = fmaxf(mx0, __shfl_xor_sync(0xffffffffu, mx0, 1));
    mx0 = fmaxf(mx0, __shfl_xor_sync(0xffffffffu, mx0, 2));
    mx1 = fmaxf(mx1, __shfl_xor_sync(0xffffffffu, mx1, 1));
    mx1 = fmaxf(mx1, __shfl_xor_sync(0xffffffffu, mx1, 2));
    float mn0 = fmaxf(mst[0], mx0), mn1 = fmaxf(mst[1], mx1);
    float al0 = __expf(mst[0] - mn0), al1 = __expf(mst[1] - mn1);
    float s0 = 0.f, s1 = 0.f;
#pragma unroll
    for (int nb = 0; nb < 8; nb++) {
        acc[nb][0] = __expf(acc[nb][0] - mn0);
        acc[nb][1] = __expf(acc[nb][1] - mn0);
        acc[nb][2] = __expf(acc[nb][2] - mn1);
        acc[nb][3] = __expf(acc[nb][3] - mn1);
        s0 += acc[nb][0] + acc[nb][1];
        s1 += acc[nb][2] + acc[nb][3];
    }
    s0 += __shfl_xor_sync(0xffffffffu, s0, 1);
    s0 += __shfl_xor_sync(0xffffffffu, s0, 2);
    s1 += __shfl_xor_sync(0xffffffffu, s1, 1);
    s1 += __shfl_xor_sync(0xffffffffu, s1, 2);
    lst[0] = lst[0] * al0 + s0;
    lst[1] = lst[1] * al1 + s1;
    mst[0] = mn0;
    mst[1] = mn1;
#pragma unroll
    for (int nb = 0; nb < 8; nb++) {
        O[nb][0] *= al0; O[nb][1] *= al0;
        O[nb][2] *= al1; O[nb][3] *= al1;
    }

    // O += P V (register-direct fp16 P fragments)
#pragma unroll
    for (int s = 0; s < 4; s++) {
        uint32_t ah[4];
        ah[0] = packh(acc[2 * s][0],     acc[2 * s][1]);
        ah[1] = packh(acc[2 * s][2],     acc[2 * s][3]);
        ah[2] = packh(acc[2 * s + 1][0], acc[2 * s + 1][1]);
        ah[3] = packh(acc[2 * s + 1][2], acc[2 * s + 1][3]);
#pragma unroll
        for (int nt2 = 0; nt2 < 4; nt2++) {
            uint32_t bv[4];
            LDSM_X4(bv[0], bv[1], bv[2], bv[3],
                    vstage + b_lane_b + (uint32_t)(nt2 * 16 * QS2 + s * 16) * 2);
            MMAH16816(O[2 * nt2],     ah, (&bv[0]));
            MMAH16816(O[2 * nt2 + 1], ah, (&bv[2]));
        }
    }
}

__global__ void __launch_bounds__(256) flash_mma(
    const __half* __restrict__ Q1f, const __half* __restrict__ Q2f,
    const __half* __restrict__ K1f, const __half* __restrict__ K2f,
    const __half* __restrict__ Vtg, const float* __restrict__ lam_p,
    __nv_bfloat16* __restrict__ Ab) {
    extern __shared__ __half sfb[];
    const uint32_t sb = smem_u32(sfb);
    const int tid = threadIdx.x, wid = tid >> 5, lane = tid & 31;
    const int qrev = gridDim.x - 1 - blockIdx.x;    // heavy CTAs first
    const int q0 = qrev * 128;
    const int h = blockIdx.y, b = blockIdx.z;
    const int bh = b * HH + h;
    const int nkv = 2 * qrev + 2;

    const __half* Q1g = Q1f + ((size_t)bh * TT + q0) * DD;
    const __half* Q2g = Q2f + ((size_t)bh * TT + q0) * DD;
    const __half* K1g = K1f + (size_t)bh * TT * DD;
    const __half* K2g = K2f + (size_t)bh * TT * DD;
    const __half* Vg  = Vtg + (size_t)bh * DD * TT;

    // Q tiles via cp.async: 128 rows x 64 fp16
    {
        int row = tid >> 1, seg = (tid & 1) * 32;
        uint32_t d1 = sb + (uint32_t)(FL_Q1 + row * QS2 + seg) * 2;
        uint32_t d2 = sb + (uint32_t)(FL_Q2 + row * QS2 + seg) * 2;
        const __half* s1 = Q1g + row * DD + seg;
        const __half* s2 = Q2g + row * DD + seg;
#pragma unroll
        for (int j = 0; j < 4; j++) { CP16(d1 + j * 16, s1 + j * 8); CP16(d2 + j * 16, s2 + j * 8); }
    }
    fl_load_kv(sb, 0, 0, tid, K1g, K2g, Vg);
    CP_COMMIT();

    float O1[8][4], O2[8][4];
#pragma unroll
    for (int nb = 0; nb < 8; nb++)
#pragma unroll
        for (int j = 0; j < 4; j++) { O1[nb][j] = 0.f; O2[nb][j] = 0.f; }
    float m1[2] = {-1e30f, -1e30f}, l1[2] = {0.f, 0.f};
    float m2[2] = {-1e30f, -1e30f}, l2[2] = {0.f, 0.f};

    const int row_g0 = q0 + wid * 16 + (lane >> 2);
    const uint32_t a_lane = (uint32_t)((lane & 15) * QS2 + (lane >> 4) * 8) * 2;
    const uint32_t aQ1 = sb + (uint32_t)(FL_Q1 + wid * 16 * QS2) * 2 + a_lane;
    const uint32_t aQ2 = sb + (uint32_t)(FL_Q2 + wid * 16 * QS2) * 2 + a_lane;
    const uint32_t b_lane_b = (uint32_t)((((lane >> 4) & 1) * 8 + (lane & 7)) * QS2 +
                                         ((lane >> 3) & 1) * 8) * 2;

    for (int kt = 0; kt < nkv; kt++) {
        if (kt + 1 < nkv) {
            fl_load_kv(sb, (kt + 1) & 1, kt + 1, tid, K1g, K2g, Vg);
            CP_COMMIT();
            CP_WAIT(1);
        } else {
            CP_WAIT(0);
        }
        __syncthreads();
        const uint32_t st = sb + (uint32_t)(FL_ST0 + (kt & 1) * FL_STAGE) * 2;
        const bool msk = (kt >= nkv - 2);
        fl_stream(aQ1, st,             st + 2 * FL_KV * 2, b_lane_b, kt, msk, row_g0, lane, O1, m1, l1);
        fl_stream(aQ2, st + FL_KV * 2, st + 2 * FL_KV * 2, b_lane_b, kt, msk, row_g0, lane, O2, m2, l2);
        __syncthreads();
    }

    // epilogue: out = O1/l1 - lam*O2/l2, write split-bf16 [hi|lo] into Ab
    float lamv = fminf(fmaxf(lam_p[h], 0.f), 1.f);
    float i10 = 1.f / l1[0], i11 = 1.f / l1[1];
    float i20 = lamv / l2[0], i21 = lamv / l2[1];
    const int row0 = q0 + wid * 16 + (lane >> 2);
    const int colb = h * 64 + 2 * (lane & 3);
    size_t rb0 = (size_t)(b * TT + row0) * KW;
    size_t rb1 = (size_t)(b * TT + row0 + 8) * KW;
#pragma unroll
    for (int nb = 0; nb < 8; nb++) {
        int col = colb + nb * 8;
        float x0 = O1[nb][0] * i10 - O2[nb][0] * i20;
        float x1 = O1[nb][1] * i10 - O2[nb][1] * i20;
        float y0 = O1[nb][2] * i11 - O2[nb][2] * i21;
        float y1 = O1[nb][3] * i11 - O2[nb][3] * i21;
        uint32_t hx = packbf(x0, x1);
        __nv_bfloat162 hv = *(__nv_bfloat162*)&hx;
        float2 hf = __bfloat1622float2(hv);
        uint32_t lx = packbf(x0 - hf.x, x1 - hf.y);
        *(uint32_t*)&Ab[rb0 + col] = hx;
        *(uint32_t*)&Ab[rb0 + 1024 + col] = lx;
        uint32_t hy = packbf(y0, y1);
        __nv_bfloat162 hv2 = *(__nv_bfloat162*)&hy;
        float2 hf2 = __bfloat1622float2(hv2);
        uint32_t ly = packbf(y0 - hf2.x, y1 - hf2.y);
        *(uint32_t*)&Ab[rb1 + col] = hy;
        *(uint32_t*)&Ab[rb1 + 1024 + col] = ly;
    }
}

// ---------------- launch ----------------
extern "C" void kernel_launch(void* const* d_in, const int* in_sizes, int n_in,
                              void* d_out, int out_size) {
    const float* x    = (const float*)d_in[0];
    const float* Wqkv = (const float*)d_in[2];
    const float* Wout = (const float*)d_in[3];
    const float* lam  = (const float*)d_in[4];
    float* out = (float*)d_out;

    __nv_bfloat16 *Ab = nullptr, *Bq = nullptr, *Bo = nullptr;
    __half *Q1f = nullptr, *Q2f = nullptr, *K1f = nullptr, *K2f = nullptr;
    __half *Vh = nullptr, *Vt = nullptr;
    cudaGetSymbolAddress((void**)&Ab,  g_Ab);
    cudaGetSymbolAddress((void**)&Bq,  g_Bq);
    cudaGetSymbolAddress((void**)&Bo,  g_Bo);
    cudaGetSymbolAddress((void**)&Q1f, g_Q1f);
    cudaGetSymbolAddress((void**)&Q2f, g_Q2f);
    cudaGetSymbolAddress((void**)&K1f, g_K1f);
    cudaGetSymbolAddress((void**)&K2f, g_K2f);
    cudaGetSymbolAddress((void**)&Vh,  g_Vh);
    cudaGetSymbolAddress((void**)&Vt,  g_Vt);

    cudaFuncSetAttribute(gemm_mma<0>, cudaFuncAttributeMaxDynamicSharedMemorySize, GEMM_SMEM);
    cudaFuncSetAttribute(gemm_mma<1>, cudaFuncAttributeMaxDynamicSharedMemorySize, GEMM_SMEM);
    cudaFuncSetAttribute(flash_mma, cudaFuncAttributeMaxDynamicSharedMemorySize, FL_SMEM_BYTES);

    // weight + input split conversions
    splitT<<<dim3(NQKV / 32, DM / 32), dim3(32, 8)>>>(Wqkv, Bq, NQKV);
    splitT<<<dim3(DM / 32, DM / 32), dim3(32, 8)>>>(Wout, Bo, DM);
    split_rows<<<(BT * DM + 255) / 256, 256>>>(x, Ab, BT * DM);

    // 1) QKV projection (bf16 3-combo, combo-outer MMA order) + fused fp16 fan-out
    gemm_mma<1><<<dim3(NQKV / 128, BT / 128), 256, GEMM_SMEM>>>(
        Ab, Bq, nullptr, NQKV, Q1f, Q2f, K1f, K2f, Vh);

    // 2) V transpose (fp16 -> fp16)
    v_transpose_h<<<dim3(TT / 64, BB * HH), 256>>>(Vh, Vt);

    // 3) dual flash attention (fp16 HMMA); writes split-bf16 attn into Ab
    flash_mma<<<dim3(TT / 128, HH, BB), 256, FL_SMEM_BYTES>>>(Q1f, Q2f, K1f, K2f, Vt, lam, Ab);

    // 4) output projection (bf16 3-combo, combo-outer MMA order), fp32 C
    gemm_mma<0><<<dim3(DM / 128, BT / 128), 256, GEMM_SMEM>>>(
        Ab, Bo, out, DM, nullptr, nullptr, nullptr, nullptr, nullptr);
}

// round 15
// speedup vs baseline: 1.5051x; 1.1796x over previous
#include <cuda_runtime.h>
#include <cuda_bf16.h>
#include <cuda_fp16.h>
#include <math.h>
#include <cstdint>

// Problem constants
#define BB 2
#define TT 2048
#define DM 1024
#define HH 16
#define DD 64
#define NQKV 5120     // H * 5 * D
#define BT  4096      // B * T
#define KW  2048      // GEMM operands: [hi(1024) | lo(1024)] bf16

// ---------------- scratch (no cudaMalloc allowed) ----------------
__device__ __align__(16) __nv_bfloat16 g_Ab[(size_t)BT * KW];          // 16.8 MB
__device__ __align__(16) __nv_bfloat16 g_Bq[(size_t)NQKV * KW];        // 21.0 MB
__device__ __align__(16) __nv_bfloat16 g_Bo[(size_t)DM * KW];          // 4.2 MB
// flash operands (fp16 single-plane): [bh][t][64], V^T [bh][d][t]
__device__ __align__(16) __half g_Q1f[(size_t)BB * HH * TT * DD];
__device__ __align__(16) __half g_Q2f[(size_t)BB * HH * TT * DD];
__device__ __align__(16) __half g_K1f[(size_t)BB * HH * TT * DD];
__device__ __align__(16) __half g_K2f[(size_t)BB * HH * TT * DD];
__device__ __align__(16) __half g_Vh [(size_t)BB * HH * TT * DD];      // V row-major fp16
__device__ __align__(16) __half g_Vt [(size_t)BB * HH * DD * TT];      // V^T

// ================= helpers (plain sm_103-safe PTX only) =================
__device__ __forceinline__ uint32_t smem_u32(const void* p) {
    uint32_t a;
    asm("{ .reg .u64 t; cvta.to.shared.u64 t, %1; cvt.u32.u64 %0, t; }" : "=r"(a) : "l"(p));
    return a;
}
#define CP16(smem, gptr) \
    asm volatile("cp.async.cg.shared.global [%0], [%1], 16;" :: "r"(smem), "l"(gptr) : "memory")
#define CP_COMMIT() asm volatile("cp.async.commit_group;" ::: "memory")
#define CP_WAIT(n)  asm volatile("cp.async.wait_group %0;" :: "n"(n) : "memory")
#define LDSM_X4(r0, r1, r2, r3, addr) \
    asm volatile("ldmatrix.sync.aligned.m8n8.x4.shared.b16 {%0,%1,%2,%3}, [%4];" \
                 : "=r"(r0), "=r"(r1), "=r"(r2), "=r"(r3) : "r"(addr))
#define MMA16816(c, a, b) \
    asm volatile("mma.sync.aligned.m16n8k16.row.col.f32.bf16.bf16.f32 " \
                 "{%0,%1,%2,%3}, {%4,%5,%6,%7}, {%8,%9}, {%0,%1,%2,%3};" \
                 : "+f"((c)[0]), "+f"((c)[1]), "+f"((c)[2]), "+f"((c)[3]) \
                 : "r"((a)[0]), "r"((a)[1]), "r"((a)[2]), "r"((a)[3]), \
                   "r"((b)[0]), "r"((b)[1]))
#define MMAH16816(c, a, b) \
    asm volatile("mma.sync.aligned.m16n8k16.row.col.f32.f16.f16.f32 " \
                 "{%0,%1,%2,%3}, {%4,%5,%6,%7}, {%8,%9}, {%0,%1,%2,%3};" \
                 : "+f"((c)[0]), "+f"((c)[1]), "+f"((c)[2]), "+f"((c)[3]) \
                 : "r"((a)[0]), "r"((a)[1]), "r"((a)[2]), "r"((a)[3]), \
                   "r"((b)[0]), "r"((b)[1]))

__device__ __forceinline__ uint32_t packbf(float lo, float hi) {
    __nv_bfloat162 t = __floats2bfloat162_rn(lo, hi);
    return *(uint32_t*)&t;
}
__device__ __forceinline__ uint32_t packh(float lo, float hi) {
    __half2 t = __floats2half2_rn(lo, hi);
    return *(uint32_t*)&t;
}

// ================= conversion kernels =================
// fp32 [M,1024] row-major -> bf16 [M,2048]: cols [0,1024)=hi [1024,2048)=lo
__global__ void __launch_bounds__(256) split_rows(const float* __restrict__ in,
                                                  __nv_bfloat16* __restrict__ out, int total) {
    int idx = blockIdx.x * 256 + threadIdx.x;
    if (idx >= total) return;
    int m = idx >> 10, k = idx & 1023;
    float v = in[idx];
    __nv_bfloat16 h = __float2bfloat16(v);
    __nv_bfloat16 l = __float2bfloat16(v - __bfloat162float(h));
    size_t rb = (size_t)m * KW;
    out[rb + k] = h;
    out[rb + 1024 + k] = l;
}

// W fp32 [1024, N] -> bf16 [N, 2048] transposed: cols [0,1024)=hi [1024,2048)=lo
__global__ void __launch_bounds__(256) splitT(const float* __restrict__ W,
                                              __nv_bfloat16* __restrict__ out, int N) {
    __shared__ float smt[32][33];
    int n0 = blockIdx.x * 32, k0 = blockIdx.y * 32;
    int tx = threadIdx.x, ty = threadIdx.y;  // 32 x 8
#pragma unroll
    for (int i = 0; i < 4; i++)
        smt[ty * 4 + i][tx] = W[(size_t)(k0 + ty * 4 + i) * N + n0 + tx];
    __syncthreads();
#pragma unroll
    for (int i = 0; i < 4; i++) {
        int nn = ty * 4 + i;
        float v = smt[tx][nn];
        __nv_bfloat16 h = __float2bfloat16(v);
        __nv_bfloat16 l = __float2bfloat16(v - __bfloat162float(h));
        size_t rb = (size_t)(n0 + nn) * KW + k0 + tx;
        out[rb] = h;
        out[rb + 1024] = l;
    }
}

// V fp16 [bh][t][64] -> V^T fp16 [bh][d][t]
__global__ void __launch_bounds__(256) v_transpose_h(const __half* __restrict__ Vh,
                                                     __half* __restrict__ Vt) {
    __shared__ __half tile[64][72];
    int t0 = blockIdx.x * 64;
    int bh = blockIdx.y;
    int c = threadIdx.x & 63, r4 = threadIdx.x >> 6;
#pragma unroll
    for (int rr = r4; rr < 64; rr += 4)
        tile[rr][c] = Vh[((size_t)bh * TT + t0 + rr) * DD + c];
    __syncthreads();
#pragma unroll
    for (int dd = r4; dd < 64; dd += 4)
        Vt[((size_t)bh * DD + dd) * TT + t0 + c] = tile[c][dd];
}

// ========== HMMA split-bf16 GEMM: C[M,N] = (Ahi+Alo)[M,1024] @ (Bhi+Blo)[N,1024]^T ==========
// 3-combo (hi*hi + hi*lo + lo*hi), 128x128 CTA tile, 16 warps (4m x 4n), warp tile 32x32.
// 512 threads -> 4 warps/SMSP for cross-warp tensor-pipe coverage.
// MODE 0: write fp32 C. MODE 1: fan out fp16 q1/q2/k1/k2/v flash operands.
#define BKC 64
#define NKI (1024 / BKC)      // 16
#define ASTR 72               // smem row stride in bf16
#define TILE_E (128 * ASTR)   // one 128x64 tile (padded)
#define STAGE_E (4 * TILE_E)  // Ahi | Alo | Bhi | Blo
#define NSTAGE 3
#define GEMM_SMEM (NSTAGE * STAGE_E * 2)   // 221184 bytes
#define GT 512

template <int MODE>
__global__ void __launch_bounds__(GT) gemm_mma(const __nv_bfloat16* __restrict__ A,
                                               const __nv_bfloat16* __restrict__ B,
                                               float* __restrict__ C, int Ntot,
                                               __half* __restrict__ Q1, __half* __restrict__ Q2,
                                               __half* __restrict__ K1, __half* __restrict__ K2,
                                               __half* __restrict__ Vh) {
    extern __shared__ __nv_bfloat16 smb[];
    const int tid = threadIdx.x;
    const int wid = tid >> 5;           // 0..15
    const int lane = tid & 31;
    const int m0 = blockIdx.y * 128;
    const int n0 = blockIdx.x * 128;
    const int wm = (wid >> 2) * 32;     // 0/32/64/96
    const int wn = (wid & 3) * 32;      // 0/32/64/96
    const uint32_t sbase = smem_u32(smb);

    // cp.async mapping: 512 threads, each loads 2x16B per 128x64 tile
    const int ldrow = tid >> 2;          // 0..127
    const int ldcol = (tid & 3) * 16;    // 0/16/32/48
    const __nv_bfloat16* Agp = A + (size_t)(m0 + ldrow) * KW + ldcol;
    const __nv_bfloat16* Bgp = B + (size_t)(n0 + ldrow) * KW + ldcol;
    const uint32_t st_off = (uint32_t)(ldrow * ASTR + ldcol) * 2;

    uint32_t aoff[2], boff[2];
#pragma unroll
    for (int mt = 0; mt < 2; mt++) {
        int row = wm + mt * 16 + (lane & 15);
        int col = (lane >> 4) * 8;
        aoff[mt] = (uint32_t)(row * ASTR + col) * 2;
    }
#pragma unroll
    for (int nt2 = 0; nt2 < 2; nt2++) {
        int n = wn + nt2 * 16 + ((lane >> 4) & 1) * 8 + (lane & 7);
        int k = ((lane >> 3) & 1) * 8;
        boff[nt2] = (uint32_t)(n * ASTR + k) * 2;
    }

    float acc[2][4][4];
#pragma unroll
    for (int mt = 0; mt < 2; mt++)
#pragma unroll
        for (int nt = 0; nt < 4; nt++)
#pragma unroll
            for (int j = 0; j < 4; j++) acc[mt][nt][j] = 0.f;

#define LOAD_STAGE(s, k0)                                                          \
    do {                                                                           \
        uint32_t _b = sbase + (uint32_t)(s) * STAGE_E * 2 + st_off;                \
        const __nv_bfloat16* _a = Agp + (k0);                                      \
        const __nv_bfloat16* _bb = Bgp + (k0);                                     \
        _Pragma("unroll")                                                          \
        for (int j = 0; j < 2; j++) {                                              \
            CP16(_b + j * 16, _a + j * 8);                                         \
            CP16(_b + TILE_E * 2 + j * 16, _a + 1024 + j * 8);                     \
            CP16(_b + 2 * TILE_E * 2 + j * 16, _bb + j * 8);                       \
            CP16(_b + 3 * TILE_E * 2 + j * 16, _bb + 1024 + j * 8);                \
        }                                                                          \
    } while (0)

#define COMBO(afr, bfr)                                                            \
    do {                                                                           \
        _Pragma("unroll")                                                          \
        for (int mt = 0; mt < 2; mt++)                                             \
            _Pragma("unroll")                                                      \
            for (int nt2 = 0; nt2 < 2; nt2++) {                                    \
                MMA16816(acc[mt][2 * nt2],     (afr)[mt], (&(bfr)[nt2][0]));       \
                MMA16816(acc[mt][2 * nt2 + 1], (afr)[mt], (&(bfr)[nt2][2]));       \
            }                                                                      \
    } while (0)

    LOAD_STAGE(0, 0);
    CP_COMMIT();
    LOAD_STAGE(1, BKC);
    CP_COMMIT();

    for (int i = 0; i < NKI; i++) {
        if (i + 1 < NKI) { CP_WAIT(1); } else { CP_WAIT(0); }
        __syncthreads();
        if (i + 2 < NKI) {
            LOAD_STAGE((i + 2) % NSTAGE, (i + 2) * BKC);
            CP_COMMIT();
        }
        const uint32_t stAh = sbase + (uint32_t)(i % NSTAGE) * STAGE_E * 2;
        const uint32_t stAl = stAh + TILE_E * 2;
        const uint32_t stBh = stAh + 2 * TILE_E * 2;
        const uint32_t stBl = stAh + 3 * TILE_E * 2;
#pragma unroll
        for (int ks = 0; ks < 4; ks++) {
            uint32_t ah[2][4], al[2][4], bh[2][4], bl[2][4];
#pragma unroll
            for (int mt = 0; mt < 2; mt++) {
                LDSM_X4(ah[mt][0], ah[mt][1], ah[mt][2], ah[mt][3], stAh + aoff[mt] + ks * 32);
                LDSM_X4(al[mt][0], al[mt][1], al[mt][2], al[mt][3], stAl + aoff[mt] + ks * 32);
            }
#pragma unroll
            for (int nt2 = 0; nt2 < 2; nt2++) {
                LDSM_X4(bh[nt2][0], bh[nt2][1], bh[nt2][2], bh[nt2][3], stBh + boff[nt2] + ks * 32);
                LDSM_X4(bl[nt2][0], bl[nt2][1], bl[nt2][2], bl[nt2][3], stBl + boff[nt2] + ks * 32);
            }
            COMBO(ah, bh);
            COMBO(ah, bl);
            COMBO(al, bh);
        }
    }
#undef LOAD_STAGE
#undef COMBO

    if (MODE == 0) {
        // fp32 C epilogue (warp covers 32 cols)
#pragma unroll
        for (int mt = 0; mt < 2; mt++) {
            int r0 = m0 + wm + mt * 16 + (lane >> 2);
            int c0 = n0 + wn + (lane & 3) * 2;
            float* p0 = C + (size_t)r0 * Ntot + c0;
            float* p1 = C + (size_t)(r0 + 8) * Ntot + c0;
#pragma unroll
            for (int nt = 0; nt < 4; nt++) {
                *(float2*)(p0 + nt * 8) = make_float2(acc[mt][nt][0], acc[mt][nt][1]);
                *(float2*)(p1 + nt * 8) = make_float2(acc[mt][nt][2], acc[mt][nt][3]);
            }
        }
    } else {
        // QKV fan-out: warp's 32 cols lie inside one 64-col segment
        const int nglob = n0 + wn;
        const int seg = nglob >> 6;        // 0..79
        const int hd  = seg / 5;
        const int part = seg % 5;
        const int segoff = nglob & 63;     // 0 or 32
        __half* dst = (part == 0) ? Q1 : (part == 1) ? Q2 : (part == 2) ? K1
                     : (part == 3) ? K2 : Vh;
        const int dcol = segoff + (lane & 3) * 2;
#pragma unroll
        for (int mt = 0; mt < 2; mt++) {
            int r0 = m0 + wm + mt * 16 + (lane >> 2);
#pragma unroll
            for (int half = 0; half < 2; half++) {
                int row = r0 + half * 8;
                int b = row >> 11, t = row & (TT - 1);
                size_t base = ((size_t)(b * HH + hd) * TT + t) * DD + dcol;
#pragma unroll
                for (int nt = 0; nt < 4; nt++) {
                    uint32_t hv = packh(acc[mt][nt][2 * half], acc[mt][nt][2 * half + 1]);
                    *(uint32_t*)&dst[base + nt * 8] = hv;
                }
            }
        }
    }
}

// ================= fp16 HMMA dual flash attention =================
// CTA: 128 q-rows of one (b,h); 8 warps, warp = m16. kv tiles of 64, double-buffered.
#define QS2 72                        // fp16 row stride (144B)
#define FL_Q1 0
#define FL_Q2 (128 * QS2)
#define FL_ST0 (2 * 128 * QS2)
#define FL_KV (64 * QS2)              // one tensor in a stage
#define FL_STAGE (3 * FL_KV)          // K1 | K2 | Vt
#define FL_SMEM_BYTES ((2 * 128 * QS2 + 2 * FL_STAGE) * 2)   // 92160

__device__ __forceinline__ void fl_load_kv(uint32_t sb, int st, int kt, int tid,
                                           const __half* K1g,
                                           const __half* K2g,
                                           const __half* Vg) {
    int r = tid >> 2, qd = tid & 3;   // row 0..63, 16-elem quarter
    uint32_t base = sb + (uint32_t)(FL_ST0 + st * FL_STAGE) * 2;
    uint32_t o = (uint32_t)(r * QS2 + qd * 16) * 2;
    const __half* k1 = K1g + (size_t)(kt * 64 + r) * DD + qd * 16;
    const __half* k2 = K2g + (size_t)(kt * 64 + r) * DD + qd * 16;
    const __half* vv = Vg + (size_t)r * TT + kt * 64 + qd * 16;
#pragma unroll
    for (int j = 0; j < 2; j++) {
        CP16(base + o + j * 16, k1 + j * 8);
        CP16(base + FL_KV * 2 + o + j * 16, k2 + j * 8);
        CP16(base + 2 * FL_KV * 2 + o + j * 16, vv + j * 8);
    }
}

// one stream: S = Q K^T (fp16), online softmax, O += P V (fp16)
__device__ __forceinline__ void fl_stream(uint32_t a_addr, uint32_t kstage, uint32_t vstage,
                                          uint32_t b_lane_b, int kt, bool need_mask,
                                          int row_g0, int lane,
                                          float O[8][4], float* mst, float* lst) {
    float acc[8][4];
#pragma unroll
    for (int nb = 0; nb < 8; nb++)
#pragma unroll
        for (int j = 0; j < 4; j++) acc[nb][j] = 0.f;

    // S = Q K^T, 4 k16 steps over D=64
#pragma unroll
    for (int s = 0; s < 4; s++) {
        uint32_t af[4];
        LDSM_X4(af[0], af[1], af[2], af[3], a_addr + s * 32);
#pragma unroll
        for (int nt2 = 0; nt2 < 4; nt2++) {
            uint32_t bf[4];
            LDSM_X4(bf[0], bf[1], bf[2], bf[3],
                    kstage + b_lane_b + (uint32_t)(nt2 * 16 * QS2 + s * 16) * 2);
            MMAH16816(acc[2 * nt2],     af, (&bf[0]));
            MMAH16816(acc[2 * nt2 + 1], af, (&bf[2]));
        }
    }

    // scale + causal mask
#pragma unroll
    for (int nb = 0; nb < 8; nb++)
#pragma unroll
        for (int j = 0; j < 4; j++) {
            float v = acc[nb][j] * 0.125f;
            if (need_mask) {
                int col = kt * 64 + nb * 8 + 2 * (lane & 3) + (j & 1);
                int row = row_g0 + ((j >> 1) << 3);
                if (col > row) v = -1e30f;
            }
            acc[nb][j] = v;
        }

    // online softmax (rows r and r+8)
    float mx0 = -1e30f, mx1 = -1e30f;
#pragma unroll
    for (int nb = 0; nb < 8; nb++) {
        mx0 = fmaxf(mx0, fmaxf(acc[nb][0], acc[nb][1]));
        mx1 = fmaxf(mx1, fmaxf(acc[nb][2], acc[nb][3]));
    }
    mx0 = fmaxf(mx0, __shfl_xor_sync(0xffffffffu, mx0, 1));
    mx0 = fmaxf(mx0, __shfl_xor_sync(0xffffffffu, mx0, 2));
    mx1 = fmaxf(mx1, __shfl_xor_sync(0xffffffffu, mx1, 1));
    mx1 = fmaxf(mx1, __shfl_xor_sync(0xffffffffu, mx1, 2));
    float mn0 = fmaxf(mst[0], mx0), mn1 = fmaxf(mst[1], mx1);
    float al0 = __expf(mst[0] - mn0), al1 = __expf(mst[1] - mn1);
    float s0 = 0.f, s1 = 0.f;
#pragma unroll
    for (int nb = 0; nb < 8; nb++) {
        acc[nb][0] = __expf(acc[nb][0] - mn0);
        acc[nb][1] = __expf(acc[nb][1] - mn0);
        acc[nb][2] = __expf(acc[nb][2] - mn1);
        acc[nb][3] = __expf(acc[nb][3] - mn1);
        s0 += acc[nb][0] + acc[nb][1];
        s1 += acc[nb][2] + acc[nb][3];
    }
    s0 += __shfl_xor_sync(0xffffffffu, s0, 1);
    s0 += __shfl_xor_sync(0xffffffffu, s0, 2);
    s1 += __shfl_xor_sync(0xffffffffu, s1, 1);
    s1 += __shfl_xor_sync(0xffffffffu, s1, 2);
    lst[0] = lst[0] * al0 + s0;
    lst[1] = lst[1] * al1 + s1;
    mst[0] = mn0;
    mst[1] = mn1;
#pragma unroll
    for (int nb = 0; nb < 8; nb++) {
        O[nb][0] *= al0; O[nb][1] *= al0;
        O[nb][2] *= al1; O[nb][3] *= al1;
    }

    // O += P V (register-direct fp16 P fragments)
#pragma unroll
    for (int s = 0; s < 4; s++) {
        uint32_t ah[4];
        ah[0] = packh(acc[2 * s][0],     acc[2 * s][1]);
        ah[1] = packh(acc[2 * s][2],     acc[2 * s][3]);
        ah[2] = packh(acc[2 * s + 1][0], acc[2 * s + 1][1]);
        ah[3] = packh(acc[2 * s + 1][2], acc[2 * s + 1][3]);
#pragma unroll
        for (int nt2 = 0; nt2 < 4; nt2++) {
            uint32_t bv[4];
            LDSM_X4(bv[0], bv[1], bv[2], bv[3],
                    vstage + b_lane_b + (uint32_t)(nt2 * 16 * QS2 + s * 16) * 2);
            MMAH16816(O[2 * nt2],     ah, (&bv[0]));
            MMAH16816(O[2 * nt2 + 1], ah, (&bv[2]));
        }
    }
}

__global__ void __launch_bounds__(256) flash_mma(
    const __half* __restrict__ Q1f, const __half* __restrict__ Q2f,
    const __half* __restrict__ K1f, const __half* __restrict__ K2f,
    const __half* __restrict__ Vtg, const float* __restrict__ lam_p,
    __nv_bfloat16* __restrict__ Ab) {
    extern __shared__ __half sfb[];
    const uint32_t sb = smem_u32(sfb);
    const int tid = threadIdx.x, wid = tid >> 5, lane = tid & 31;
    const int qrev = gridDim.x - 1 - blockIdx.x;    // heavy CTAs first
    const int q0 = qrev * 128;
    const int h = blockIdx.y, b = blockIdx.z;
    const int bh = b * HH + h;
    const int nkv = 2 * qrev + 2;

    const __half* Q1g = Q1f + ((size_t)bh * TT + q0) * DD;
    const __half* Q2g = Q2f + ((size_t)bh * TT + q0) * DD;
    const __half* K1g = K1f + (size_t)bh * TT * DD;
    const __half* K2g = K2f + (size_t)bh * TT * DD;
    const __half* Vg  = Vtg + (size_t)bh * DD * TT;

    // Q tiles via cp.async: 128 rows x 64 fp16
    {
        int row = tid >> 1, seg = (tid & 1) * 32;
        uint32_t d1 = sb + (uint32_t)(FL_Q1 + row * QS2 + seg) * 2;
        uint32_t d2 = sb + (uint32_t)(FL_Q2 + row * QS2 + seg) * 2;
        const __half* s1 = Q1g + row * DD + seg;
        const __half* s2 = Q2g + row * DD + seg;
#pragma unroll
        for (int j = 0; j < 4; j++) { CP16(d1 + j * 16, s1 + j * 8); CP16(d2 + j * 16, s2 + j * 8); }
    }
    fl_load_kv(sb, 0, 0, tid, K1g, K2g, Vg);
    CP_COMMIT();

    float O1[8][4], O2[8][4];
#pragma unroll
    for (int nb = 0; nb < 8; nb++)
#pragma unroll
        for (int j = 0; j < 4; j++) { O1[nb][j] = 0.f; O2[nb][j] = 0.f; }
    float m1[2] = {-1e30f, -1e30f}, l1[2] = {0.f, 0.f};
    float m2[2] = {-1e30f, -1e30f}, l2[2] = {0.f, 0.f};

    const int row_g0 = q0 + wid * 16 + (lane >> 2);
    const uint32_t a_lane = (uint32_t)((lane & 15) * QS2 + (lane >> 4) * 8) * 2;
    const uint32_t aQ1 = sb + (uint32_t)(FL_Q1 + wid * 16 * QS2) * 2 + a_lane;
    const uint32_t aQ2 = sb + (uint32_t)(FL_Q2 + wid * 16 * QS2) * 2 + a_lane;
    const uint32_t b_lane_b = (uint32_t)((((lane >> 4) & 1) * 8 + (lane & 7)) * QS2 +
                                         ((lane >> 3) & 1) * 8) * 2;

    for (int kt = 0; kt < nkv; kt++) {
        if (kt + 1 < nkv) {
            fl_load_kv(sb, (kt + 1) & 1, kt + 1, tid, K1g, K2g, Vg);
            CP_COMMIT();
            CP_WAIT(1);
        } else {
            CP_WAIT(0);
        }
        __syncthreads();
        const uint32_t st = sb + (uint32_t)(FL_ST0 + (kt & 1) * FL_STAGE) * 2;
        const bool msk = (kt >= nkv - 2);
        fl_stream(aQ1, st,             st + 2 * FL_KV * 2, b_lane_b, kt, msk, row_g0, lane, O1, m1, l1);
        fl_stream(aQ2, st + FL_KV * 2, st + 2 * FL_KV * 2, b_lane_b, kt, msk, row_g0, lane, O2, m2, l2);
        __syncthreads();
    }

    // epilogue: out = O1/l1 - lam*O2/l2, write split-bf16 [hi|lo] into Ab
    float lamv = fminf(fmaxf(lam_p[h], 0.f), 1.f);
    float i10 = 1.f / l1[0], i11 = 1.f / l1[1];
    float i20 = lamv / l2[0], i21 = lamv / l2[1];
    const int row0 = q0 + wid * 16 + (lane >> 2);
    const int colb = h * 64 + 2 * (lane & 3);
    size_t rb0 = (size_t)(b * TT + row0) * KW;
    size_t rb1 = (size_t)(b * TT + row0 + 8) * KW;
#pragma unroll
    for (int nb = 0; nb < 8; nb++) {
        int col = colb + nb * 8;
        float x0 = O1[nb][0] * i10 - O2[nb][0] * i20;
        float x1 = O1[nb][1] * i10 - O2[nb][1] * i20;
        float y0 = O1[nb][2] * i11 - O2[nb][2] * i21;
        float y1 = O1[nb][3] * i11 - O2[nb][3] * i21;
        uint32_t hx = packbf(x0, x1);
        __nv_bfloat162 hv = *(__nv_bfloat162*)&hx;
        float2 hf = __bfloat1622float2(hv);
        uint32_t lx = packbf(x0 - hf.x, x1 - hf.y);
        *(uint32_t*)&Ab[rb0 + col] = hx;
        *(uint32_t*)&Ab[rb0 + 1024 + col] = lx;
        uint32_t hy = packbf(y0, y1);
        __nv_bfloat162 hv2 = *(__nv_bfloat162*)&hy;
        float2 hf2 = __bfloat1622float2(hv2);
        uint32_t ly = packbf(y0 - hf2.x, y1 - hf2.y);
        *(uint32_t*)&Ab[rb1 + col] = hy;
        *(uint32_t*)&Ab[rb1 + 1024 + col] = ly;
    }
}

// ---------------- launch ----------------
extern "C" void kernel_launch(void* const* d_in, const int* in_sizes, int n_in,
                              void* d_out, int out_size) {
    const float* x    = (const float*)d_in[0];
    const float* Wqkv = (const float*)d_in[2];
    const float* Wout = (const float*)d_in[3];
    const float* lam  = (const float*)d_in[4];
    float* out = (float*)d_out;

    __nv_bfloat16 *Ab = nullptr, *Bq = nullptr, *Bo = nullptr;
    __half *Q1f = nullptr, *Q2f = nullptr, *K1f = nullptr, *K2f = nullptr;
    __half *Vh = nullptr, *Vt = nullptr;
    cudaGetSymbolAddress((void**)&Ab,  g_Ab);
    cudaGetSymbolAddress((void**)&Bq,  g_Bq);
    cudaGetSymbolAddress((void**)&Bo,  g_Bo);
    cudaGetSymbolAddress((void**)&Q1f, g_Q1f);
    cudaGetSymbolAddress((void**)&Q2f, g_Q2f);
    cudaGetSymbolAddress((void**)&K1f, g_K1f);
    cudaGetSymbolAddress((void**)&K2f, g_K2f);
    cudaGetSymbolAddress((void**)&Vh,  g_Vh);
    cudaGetSymbolAddress((void**)&Vt,  g_Vt);

    cudaFuncSetAttribute(gemm_mma<0>, cudaFuncAttributeMaxDynamicSharedMemorySize, GEMM_SMEM);
    cudaFuncSetAttribute(gemm_mma<1>, cudaFuncAttributeMaxDynamicSharedMemorySize, GEMM_SMEM);
    cudaFuncSetAttribute(flash_mma, cudaFuncAttributeMaxDynamicSharedMemorySize, FL_SMEM_BYTES);

    // weight + input split conversions
    splitT<<<dim3(NQKV / 32, DM / 32), dim3(32, 8)>>>(Wqkv, Bq, NQKV);
    splitT<<<dim3(DM / 32, DM / 32), dim3(32, 8)>>>(Wout, Bo, DM);
    split_rows<<<(BT * DM + 255) / 256, 256>>>(x, Ab, BT * DM);

    // 1) QKV projection (bf16 3-combo, 16 warps/CTA) + fused fp16 fan-out
    gemm_mma<1><<<dim3(NQKV / 128, BT / 128), GT, GEMM_SMEM>>>(
        Ab, Bq, nullptr, NQKV, Q1f, Q2f, K1f, K2f, Vh);

    // 2) V transpose (fp16 -> fp16)
    v_transpose_h<<<dim3(TT / 64, BB * HH), 256>>>(Vh, Vt);

    // 3) dual flash attention (fp16 HMMA); writes split-bf16 attn into Ab
    flash_mma<<<dim3(TT / 128, HH, BB), 256, FL_SMEM_BYTES>>>(Q1f, Q2f, K1f, K2f, Vt, lam, Ab);

    // 4) output projection (bf16 3-combo, 16 warps/CTA), fp32 C
    gemm_mma<0><<<dim3(DM / 128, BT / 128), GT, GEMM_SMEM>>>(
        Ab, Bo, out, DM, nullptr, nullptr, nullptr, nullptr, nullptr);
}